// round 3
// baseline (speedup 1.0000x reference)
#include <cuda_runtime.h>
#include <cmath>

#define S_LEN  1024
#define BATCHN 128
#define IDIM   256
#define HDIM   512
#define ODIM   64

typedef unsigned long long ull;

// ---------- f32x2 packed helpers ----------
__device__ __forceinline__ ull splat2(float x) {
    ull r; asm("mov.b64 %0, {%1, %1};" : "=l"(r) : "f"(x)); return r;
}
__device__ __forceinline__ ull ffma2(ull a, ull b, ull c) {
    ull d; asm("fma.rn.f32x2 %0, %1, %2, %3;" : "=l"(d) : "l"(a), "l"(b), "l"(c)); return d;
}
__device__ __forceinline__ ull add2(ull a, ull b) {
    ull d; asm("add.rn.f32x2 %0, %1, %2;" : "=l"(d) : "l"(a), "l"(b)); return d;
}
__device__ __forceinline__ float2 upk2(ull v) {
    float2 f; asm("mov.b64 {%0, %1}, %2;" : "=f"(f.x), "=f"(f.y) : "l"(v)); return f;
}

// ---------- scratch (device globals: allocation-free rule) ----------
__device__ float g_xp[(size_t)BATCHN * S_LEN * HDIM];  // X@W_ih + b_hh, [b][s][h]
__device__ float g_h [(size_t)BATCHN * S_LEN * HDIM];  // hidden states,  [b][s][h]

// ============================================================================
// Kernel A: g_xp[M,512] = X[M,256] @ W_ih[256,512] + b_hh, M = 131072
// ============================================================================
__global__ void __launch_bounds__(256, 2) xproj_kernel(
    const float* __restrict__ X, const float* __restrict__ Wih,
    const float* __restrict__ bhh)
{
    __shared__ float As[128][17];
    __shared__ float Bs[16][128];
    const int tid = threadIdx.x;
    const int m0 = blockIdx.x * 128;
    const int n0 = blockIdx.y * 128;
    const int tx = tid & 15, ty = tid >> 4;

    ull acc[8][4];
#pragma unroll
    for (int i = 0; i < 8; i++)
#pragma unroll
        for (int j = 0; j < 4; j++) acc[i][j] = 0ull;

    for (int k0 = 0; k0 < IDIM; k0 += 16) {
#pragma unroll
        for (int i = 0; i < 2; i++) {
            int f4  = tid + i * 256;
            int row = f4 >> 2;
            int c4  = (f4 & 3) << 2;
            float4 v = *(const float4*)(X + (size_t)(m0 + row) * IDIM + k0 + c4);
            As[row][c4 + 0] = v.x; As[row][c4 + 1] = v.y;
            As[row][c4 + 2] = v.z; As[row][c4 + 3] = v.w;
        }
#pragma unroll
        for (int i = 0; i < 2; i++) {
            int f4  = tid + i * 256;
            int row = f4 >> 5;
            int c4  = (f4 & 31) << 2;
            *(float4*)&Bs[row][c4] =
                *(const float4*)(Wih + (size_t)(k0 + row) * HDIM + n0 + c4);
        }
        __syncthreads();
#pragma unroll
        for (int k = 0; k < 16; k++) {
            ulonglong2 bv0 = *(const ulonglong2*)&Bs[k][tx * 4];
            ulonglong2 bv1 = *(const ulonglong2*)&Bs[k][64 + tx * 4];
#pragma unroll
            for (int i = 0; i < 8; i++) {
                ull a2 = splat2(As[ty * 8 + i][k]);
                acc[i][0] = ffma2(a2, bv0.x, acc[i][0]);
                acc[i][1] = ffma2(a2, bv0.y, acc[i][1]);
                acc[i][2] = ffma2(a2, bv1.x, acc[i][2]);
                acc[i][3] = ffma2(a2, bv1.y, acc[i][3]);
            }
        }
        __syncthreads();
    }

#pragma unroll
    for (int i = 0; i < 8; i++) {
        float* dst = g_xp + (size_t)(m0 + ty * 8 + i) * HDIM + n0;
#pragma unroll
        for (int j = 0; j < 4; j++) {
            int n = (j < 2) ? (tx * 4 + j * 2) : (64 + tx * 4 + (j - 2) * 2);
            float2 v = upk2(acc[i][j]);
            v.x += bhh[n0 + n];
            v.y += bhh[n0 + n + 1];
            *(float2*)(dst + n) = v;
        }
    }
}

// ============================================================================
// Kernel B: serial recurrence, col-pair packed f32x2, h pre-splatted in smem,
// inter-CTA h exchange via L2 (g_h) + cluster.sync.
// 16 clusters x 8 CTAs; rank r owns W_hh cols [64r,64r+64) as ull pairs in
// smem; cluster g owns batch rows [8g,8g+8).
// ============================================================================
#define NT 256
// float offsets: Ws2 ull[512][32] = 32768 f | hs ull[512][10] = 10240 f | part ull[8][8][32] = 4096 f
#define OFF_HS   32768
#define OFF_PART 43008
#define SMEMB_FLOATS (43008 + 4096)
#define SMEMB_BYTES  (SMEMB_FLOATS * 4)
#define BSTRIDE ((size_t)S_LEN * HDIM)

__global__ void __launch_bounds__(NT, 1) __cluster_dims__(8, 1, 1)
rnn_kernel(const float* __restrict__ Whh)
{
    extern __shared__ float sm[];
    float* Wsf = sm;             // [k][jp] as ull pairs (cols 2jp,2jp+1)
    float* hsf = sm + OFF_HS;    // [k][b] splatted ulls, row stride 10 ull (pad)
    ull*   prt = (ull*)(sm + OFF_PART);  // [w][b][jp]

    const int tid  = threadIdx.x;
    const int rank = blockIdx.x & 7;
    const int g    = blockIdx.x >> 3;
    const int c0   = rank * 64;

    // Load W_hh slice once as column pairs (128KB)
    for (int i = tid; i < HDIM * 32; i += NT) {
        int k = i >> 5, jp = i & 31;
        *(float2*)(Wsf + 2 * i) =
            *(const float2*)(Whh + (size_t)k * HDIM + c0 + 2 * jp);
    }
    // hs = splat(h0 = 0)
    for (int i = tid; i < HDIM * 20; i += NT) hsf[i] = 0.f;
    __syncthreads();
    asm volatile("barrier.cluster.arrive.aligned;" ::: "memory");
    asm volatile("barrier.cluster.wait.aligned;"   ::: "memory");

    const int w = tid >> 5, l = tid & 31;
    const int jp = l;
    const int kbeg = w * 64;

    // phase-1 pointers
    const float* wsp = Wsf + (size_t)kbeg * 64 + jp * 2;
    const float* hsp = hsf + kbeg * 20;
    ull*       pw   = prt + w * 256 + jp;

    // phase-2 (reduce) mapping: warp -> batch, lane -> col pair
    const size_t bg = (size_t)(g * 8 + w);
    const float* xpp = g_xp + bg * BSTRIDE + c0 + 2 * jp;
    float*       ghw = g_h  + bg * BSTRIDE + c0 + 2 * jp;
    const ull*   pr  = prt + w * 32 + jp;

    // splat-pass base: batch 0 of this cluster
    const float* ghr0 = g_h + (size_t)(g * 8) * BSTRIDE;

    for (int t = 0; t < S_LEN; t++) {
        // prefetch xp pair (consumed ~2.5k cyc later in phase 2)
        ull xv = *(const ull*)(xpp + (size_t)t * HDIM);

        // ---- phase 1: acc[b] (col-pair) += W[k][pair] * splat(h[k][b]) ----
        ull a0 = 0, a1 = 0, a2 = 0, a3 = 0, a4 = 0, a5 = 0, a6 = 0, a7 = 0;
#pragma unroll 4
        for (int k = 0; k < 64; k++) {
            ull wv = *(const ull*)(wsp + k * 64);
            const ull* hk = (const ull*)(hsp + k * 20);
            ulonglong2 h01 = *(const ulonglong2*)(hk + 0);
            ulonglong2 h23 = *(const ulonglong2*)(hk + 2);
            ulonglong2 h45 = *(const ulonglong2*)(hk + 4);
            ulonglong2 h67 = *(const ulonglong2*)(hk + 6);
            a0 = ffma2(wv, h01.x, a0);
            a1 = ffma2(wv, h01.y, a1);
            a2 = ffma2(wv, h23.x, a2);
            a3 = ffma2(wv, h23.y, a3);
            a4 = ffma2(wv, h45.x, a4);
            a5 = ffma2(wv, h45.y, a5);
            a6 = ffma2(wv, h67.x, a6);
            a7 = ffma2(wv, h67.y, a7);
        }
        pw[0]   = a0; pw[32]  = a1; pw[64]  = a2; pw[96]  = a3;
        pw[128] = a4; pw[160] = a5; pw[192] = a6; pw[224] = a7;
        __syncthreads();

        // ---- phase 2: reduce over 8 k-chunks, + xp, tanh, publish to L2 ----
        ull s = xv;
        s = add2(s, pr[0]);    s = add2(s, pr[256]);
        s = add2(s, pr[512]);  s = add2(s, pr[768]);
        s = add2(s, pr[1024]); s = add2(s, pr[1280]);
        s = add2(s, pr[1536]); s = add2(s, pr[1792]);
        float2 sv = upk2(s);
        float2 hv;
        hv.x = tanhf(sv.x);
        hv.y = tanhf(sv.y);
        *(float2*)(ghw + (size_t)t * HDIM) = hv;

        // cluster-scope release/acquire: peers' g_h writes visible after this
        asm volatile("barrier.cluster.arrive.aligned;" ::: "memory");
        asm volatile("barrier.cluster.wait.aligned;"   ::: "memory");

        // ---- receive + splat h_t into hs (own k-chunk only -> no syncthreads) ----
        {
            const float* gb = ghr0 + (size_t)t * HDIM;
#pragma unroll
            for (int kk = 0; kk < 2; kk++) {
                int k = kbeg + kk * 32 + l;
                const float* gk = gb + k;
                float f0 = gk[0 * BSTRIDE], f1 = gk[1 * BSTRIDE];
                float f2 = gk[2 * BSTRIDE], f3 = gk[3 * BSTRIDE];
                const float* gk4 = gk + 4 * BSTRIDE;
                float f4 = gk4[0 * BSTRIDE], f5 = gk4[1 * BSTRIDE];
                float f6 = gk4[2 * BSTRIDE], f7 = gk4[3 * BSTRIDE];
                float* hd = hsf + k * 20;
                *(float4*)(hd + 0)  = make_float4(f0, f0, f1, f1);
                *(float4*)(hd + 4)  = make_float4(f2, f2, f3, f3);
                *(float4*)(hd + 8)  = make_float4(f4, f4, f5, f5);
                *(float4*)(hd + 12) = make_float4(f6, f6, f7, f7);
            }
        }
    }
}

// ============================================================================
// Kernel C: out[M,64] = g_h[M,512] @ W_ho[512,64] + b_ho, M = 131072
// ============================================================================
__global__ void __launch_bounds__(256) out_kernel(
    const float* __restrict__ Who, const float* __restrict__ bho,
    float* __restrict__ out)
{
    __shared__ float As[128][17];
    __shared__ float Bs[16][64];
    const int tid = threadIdx.x;
    const int m0 = blockIdx.x * 128;
    const int tx = tid & 15, ty = tid >> 4;

    ull acc[8][2];
#pragma unroll
    for (int i = 0; i < 8; i++) { acc[i][0] = 0ull; acc[i][1] = 0ull; }

    for (int k0 = 0; k0 < HDIM; k0 += 16) {
#pragma unroll
        for (int i = 0; i < 2; i++) {
            int f4  = tid + i * 256;
            int row = f4 >> 2;
            int c4  = (f4 & 3) << 2;
            float4 v = *(const float4*)(g_h + (size_t)(m0 + row) * HDIM + k0 + c4);
            As[row][c4 + 0] = v.x; As[row][c4 + 1] = v.y;
            As[row][c4 + 2] = v.z; As[row][c4 + 3] = v.w;
        }
        {
            int row = tid >> 4;
            int c4  = (tid & 15) << 2;
            *(float4*)&Bs[row][c4] =
                *(const float4*)(Who + (size_t)(k0 + row) * ODIM + c4);
        }
        __syncthreads();
#pragma unroll
        for (int k = 0; k < 16; k++) {
            ulonglong2 bv = *(const ulonglong2*)&Bs[k][tx * 4];
#pragma unroll
            for (int i = 0; i < 8; i++) {
                ull a2 = splat2(As[ty * 8 + i][k]);
                acc[i][0] = ffma2(a2, bv.x, acc[i][0]);
                acc[i][1] = ffma2(a2, bv.y, acc[i][1]);
            }
        }
        __syncthreads();
    }

    float bb0 = bho[tx * 4 + 0], bb1 = bho[tx * 4 + 1];
    float bb2 = bho[tx * 4 + 2], bb3 = bho[tx * 4 + 3];
#pragma unroll
    for (int i = 0; i < 8; i++) {
        float2 v0 = upk2(acc[i][0]); v0.x += bb0; v0.y += bb1;
        float2 v1 = upk2(acc[i][1]); v1.x += bb2; v1.y += bb3;
        float* dst = out + (size_t)(m0 + ty * 8 + i) * ODIM + tx * 4;
        *(float2*)(dst + 0) = v0;
        *(float2*)(dst + 2) = v1;
    }
}

// ============================================================================
extern "C" void kernel_launch(void* const* d_in, const int* in_sizes, int n_in,
                              void* d_out, int out_size)
{
    const float* X   = (const float*)d_in[0];   // [128,1024,256]
    const float* Whh = (const float*)d_in[1];   // [512,512]
    const float* Wih = (const float*)d_in[2];   // [256,512]
    const float* bhh = (const float*)d_in[3];   // [512]
    const float* Who = (const float*)d_in[4];   // [512,64]
    const float* bho = (const float*)d_in[5];   // [64]
    float* out = (float*)d_out;                 // [128,1024,64]

    cudaFuncSetAttribute(rnn_kernel,
                         cudaFuncAttributeMaxDynamicSharedMemorySize,
                         SMEMB_BYTES);

    xproj_kernel<<<dim3(1024, 4, 1), 256>>>(X, Wih, bhh);
    rnn_kernel<<<128, 256, SMEMB_BYTES>>>(Whh);
    out_kernel<<<1024, 256>>>(Who, bho, out);
}

// round 4
// speedup vs baseline: 1.0972x; 1.0972x over previous
#include <cuda_runtime.h>
#include <cmath>

#define S_LEN  1024
#define BATCHN 128
#define IDIM   256
#define HDIM   512
#define ODIM   64

typedef unsigned long long ull;

// ---------- f32x2 packed helpers ----------
__device__ __forceinline__ ull splat2(float x) {
    ull r; asm("mov.b64 %0, {%1, %1};" : "=l"(r) : "f"(x)); return r;
}
__device__ __forceinline__ ull ffma2(ull a, ull b, ull c) {
    ull d; asm("fma.rn.f32x2 %0, %1, %2, %3;" : "=l"(d) : "l"(a), "l"(b), "l"(c)); return d;
}
__device__ __forceinline__ ull add2(ull a, ull b) {
    ull d; asm("add.rn.f32x2 %0, %1, %2;" : "=l"(d) : "l"(a), "l"(b)); return d;
}
__device__ __forceinline__ float2 upk2(ull v) {
    float2 f; asm("mov.b64 {%0, %1}, %2;" : "=f"(f.x), "=f"(f.y) : "l"(v)); return f;
}
__device__ __forceinline__ unsigned s2u32(const void* p) {
    unsigned a;
    asm("{ .reg .u64 t; cvta.to.shared.u64 t, %1; cvt.u32.u64 %0, t; }" : "=r"(a) : "l"(p));
    return a;
}
__device__ __forceinline__ unsigned mapa_rank(unsigned a, unsigned r) {
    unsigned d; asm("mapa.shared::cluster.u32 %0, %1, %2;" : "=r"(d) : "r"(a), "r"(r));
    return d;
}

// ---------- scratch (device globals: allocation-free rule) ----------
__device__ float g_xp[(size_t)BATCHN * S_LEN * HDIM];  // X@W_ih + b_hh, [b][s][h]
__device__ float g_h [(size_t)BATCHN * S_LEN * HDIM];  // hidden states,  [b][s][h]

// ============================================================================
// Kernel A: g_xp[M,512] = X[M,256] @ W_ih[256,512] + b_hh, M = 131072
// ============================================================================
__global__ void __launch_bounds__(256, 2) xproj_kernel(
    const float* __restrict__ X, const float* __restrict__ Wih,
    const float* __restrict__ bhh)
{
    __shared__ float As[128][17];
    __shared__ float Bs[16][128];
    const int tid = threadIdx.x;
    const int m0 = blockIdx.x * 128;
    const int n0 = blockIdx.y * 128;
    const int tx = tid & 15, ty = tid >> 4;

    ull acc[8][4];
#pragma unroll
    for (int i = 0; i < 8; i++)
#pragma unroll
        for (int j = 0; j < 4; j++) acc[i][j] = 0ull;

    for (int k0 = 0; k0 < IDIM; k0 += 16) {
#pragma unroll
        for (int i = 0; i < 2; i++) {
            int f4  = tid + i * 256;
            int row = f4 >> 2;
            int c4  = (f4 & 3) << 2;
            float4 v = *(const float4*)(X + (size_t)(m0 + row) * IDIM + k0 + c4);
            As[row][c4 + 0] = v.x; As[row][c4 + 1] = v.y;
            As[row][c4 + 2] = v.z; As[row][c4 + 3] = v.w;
        }
#pragma unroll
        for (int i = 0; i < 2; i++) {
            int f4  = tid + i * 256;
            int row = f4 >> 5;
            int c4  = (f4 & 31) << 2;
            *(float4*)&Bs[row][c4] =
                *(const float4*)(Wih + (size_t)(k0 + row) * HDIM + n0 + c4);
        }
        __syncthreads();
#pragma unroll
        for (int k = 0; k < 16; k++) {
            ulonglong2 bv0 = *(const ulonglong2*)&Bs[k][tx * 4];
            ulonglong2 bv1 = *(const ulonglong2*)&Bs[k][64 + tx * 4];
#pragma unroll
            for (int i = 0; i < 8; i++) {
                ull a2 = splat2(As[ty * 8 + i][k]);
                acc[i][0] = ffma2(a2, bv0.x, acc[i][0]);
                acc[i][1] = ffma2(a2, bv0.y, acc[i][1]);
                acc[i][2] = ffma2(a2, bv1.x, acc[i][2]);
                acc[i][3] = ffma2(a2, bv1.y, acc[i][3]);
            }
        }
        __syncthreads();
    }

#pragma unroll
    for (int i = 0; i < 8; i++) {
        float* dst = g_xp + (size_t)(m0 + ty * 8 + i) * HDIM + n0;
#pragma unroll
        for (int j = 0; j < 4; j++) {
            int n = (j < 2) ? (tx * 4 + j * 2) : (64 + tx * 4 + (j - 2) * 2);
            float2 v = upk2(acc[i][j]);
            v.x += bhh[n0 + n];
            v.y += bhh[n0 + n + 1];
            *(float2*)(dst + n) = v;
        }
    }
}

// empty launch to shift ncu's fixed profiled-launch slot onto rnn_kernel
__global__ void dummy_kernel() {}

// ============================================================================
// Kernel B: serial recurrence.
// 16 clusters x 8 CTAs; rank r owns W_hh cols [64r,64r+64) as ull col-pairs
// in smem; cluster g owns batch rows [8g,8g+8).
// Per step:
//   phase1: warp w computes k-chunk [64w,64w+64) partial col-pair dots.
//           W: LDS.64 lane-contiguous; h: broadcast LDS.128 from pre-splatted
//           hsf[k][b] (row stride 10 ull for alignment + conflict spread).
//   phase2: reduce over 8 warps (+xp), tanh, STG h to g_h (for kernel C),
//           DSMEM-push compact h pair to hx[nxt][b][k] in all 8 cluster CTAs,
//           cluster.sync, then each warp splats its own k-chunk hx->hsf.
// ============================================================================
#define NT 256
// float offsets
#define OFF_HSF 32768                 // ull[512][10]  (40960 B)
#define OFF_HX  43008                 // f32[2][8][512] (32768 B)
#define OFF_PRT 51200                 // ull[8][8][32]  (16384 B)
#define SMEMB_FLOATS (51200 + 4096)
#define SMEMB_BYTES  (SMEMB_FLOATS * 4)
#define BSTRIDE ((size_t)S_LEN * HDIM)

__global__ void __launch_bounds__(NT, 1) __cluster_dims__(8, 1, 1)
rnn_kernel(const float* __restrict__ Whh)
{
    extern __shared__ float sm[];
    ull* Wp  = (ull*)sm;               // [k][jp], k stride 32 ull
    ull* hsf = (ull*)(sm + OFF_HSF);   // [k][b], k stride 10 ull (pad)
    ull* prt = (ull*)(sm + OFF_PRT);   // [w][b][jp]

    const int tid  = threadIdx.x;
    const int rank = blockIdx.x & 7;
    const int g    = blockIdx.x >> 3;
    const int c0   = rank * 64;

    // Load W_hh slice once as column pairs (128KB)
    for (int i = tid; i < HDIM * 32; i += NT) {
        int k = i >> 5, jp = i & 31;
        *(float2*)(Wp + i) = *(const float2*)(Whh + (size_t)k * HDIM + c0 + 2 * jp);
    }
    // zero hsf + hx (h0 = 0)
    for (int i = tid; i < HDIM * 20 + 2 * 8 * HDIM; i += NT) sm[OFF_HSF + i] = 0.f;
    __syncthreads();
    asm volatile("barrier.cluster.arrive.aligned;" ::: "memory");
    asm volatile("barrier.cluster.wait.aligned;"   ::: "memory");

    const int w = tid >> 5, l = tid & 31;
    const int kbeg = w * 64;

    // phase-1 pointers
    const ull* wsp = Wp + (size_t)kbeg * 32 + l;  // wv at wsp[k*32]
    const ull* hsp = hsf + (size_t)kbeg * 10;     // hk at hsp + k*10
    ull*       pw  = prt + w * 256 + l;           // partial out: pw[b*32]

    // phase-2 mapping: warp -> batch b=w, lane -> col pair jp=l
    const ull* pr  = prt + w * 32 + l;            // reduce in: pr[w'*256]
    const float* xpp = g_xp + ((size_t)(g * 8 + w)) * BSTRIDE + c0 + 2 * l;
    float*       ghw = g_h  + ((size_t)(g * 8 + w)) * BSTRIDE + c0 + 2 * l;

    // DSMEM push targets: hx[0][b=w][c0+2l] in each rank
    unsigned hx_loc = s2u32(sm) + (unsigned)((OFF_HX + w * HDIM + c0 + 2 * l) * 4);
    unsigned peer[8];
#pragma unroll
    for (int r = 0; r < 8; r++) peer[r] = mapa_rank(hx_loc, (unsigned)r);

    // splat-pass pointers: warp w covers k in [kbeg, kbeg+64): lane does
    // k = kbeg+l and kbeg+32+l for all 8 batches.
    const float* spl_src = sm + OFF_HX + kbeg + l;       // + nxt*4096 + b*512 (+32)
    ull*         spl_dst = hsf + (size_t)(kbeg + l) * 10; // [ +b ], k+32 -> +320

    for (int t = 0; t < S_LEN; t++) {
        const int nxt = (t & 1) ^ 1;
        // prefetch xp pair (consumed after phase 1)
        ull xv = *(const ull*)(xpp + (size_t)t * HDIM);

        // ---- phase 1 ----
        ull a0 = 0, a1 = 0, a2 = 0, a3 = 0, a4 = 0, a5 = 0, a6 = 0, a7 = 0;
#pragma unroll 2
        for (int k = 0; k < 64; k++) {
            ull wv = wsp[k * 32];
            const ull* hk = hsp + k * 10;
            ulonglong2 h01 = *(const ulonglong2*)(hk + 0);
            ulonglong2 h23 = *(const ulonglong2*)(hk + 2);
            ulonglong2 h45 = *(const ulonglong2*)(hk + 4);
            ulonglong2 h67 = *(const ulonglong2*)(hk + 6);
            a0 = ffma2(wv, h01.x, a0);
            a1 = ffma2(wv, h01.y, a1);
            a2 = ffma2(wv, h23.x, a2);
            a3 = ffma2(wv, h23.y, a3);
            a4 = ffma2(wv, h45.x, a4);
            a5 = ffma2(wv, h45.y, a5);
            a6 = ffma2(wv, h67.x, a6);
            a7 = ffma2(wv, h67.y, a7);
        }
        pw[0]   = a0; pw[32]  = a1; pw[64]  = a2; pw[96]  = a3;
        pw[128] = a4; pw[160] = a5; pw[192] = a6; pw[224] = a7;
        __syncthreads();

        // ---- phase 2: reduce + tanh + publish ----
        ull s = xv;
        s = add2(s, pr[0]);    s = add2(s, pr[256]);
        s = add2(s, pr[512]);  s = add2(s, pr[768]);
        s = add2(s, pr[1024]); s = add2(s, pr[1280]);
        s = add2(s, pr[1536]); s = add2(s, pr[1792]);
        float2 sv = upk2(s);
        float hx0 = tanhf(sv.x);
        float hx1 = tanhf(sv.y);
        *(float2*)(ghw + (size_t)t * HDIM) = make_float2(hx0, hx1);

        const unsigned boff = (unsigned)(nxt * (8 * HDIM * 4));
#pragma unroll
        for (int r = 0; r < 8; r++) {
            asm volatile("st.shared::cluster.v2.f32 [%0], {%1, %2};"
                         :: "r"(peer[r] + boff), "f"(hx0), "f"(hx1) : "memory");
        }
        asm volatile("barrier.cluster.arrive.aligned;" ::: "memory");
        asm volatile("barrier.cluster.wait.aligned;"   ::: "memory");

        // ---- splat own k-chunk hx[nxt] -> hsf (own-warp data, no sync) ----
        {
            const float* src = spl_src + nxt * (8 * HDIM);
#pragma unroll
            for (int b = 0; b < 8; b++) {
                float f0 = src[b * HDIM];
                float f1 = src[b * HDIM + 32];
                spl_dst[b]       = splat2(f0);
                spl_dst[320 + b] = splat2(f1);
            }
        }
    }
}

// ============================================================================
// Kernel C: out[M,64] = g_h[M,512] @ W_ho[512,64] + b_ho, M = 131072
// ============================================================================
__global__ void __launch_bounds__(256) out_kernel(
    const float* __restrict__ Who, const float* __restrict__ bho,
    float* __restrict__ out)
{
    __shared__ float As[128][17];
    __shared__ float Bs[16][64];
    const int tid = threadIdx.x;
    const int m0 = blockIdx.x * 128;
    const int tx = tid & 15, ty = tid >> 4;

    ull acc[8][2];
#pragma unroll
    for (int i = 0; i < 8; i++) { acc[i][0] = 0ull; acc[i][1] = 0ull; }

    for (int k0 = 0; k0 < HDIM; k0 += 16) {
#pragma unroll
        for (int i = 0; i < 2; i++) {
            int f4  = tid + i * 256;
            int row = f4 >> 2;
            int c4  = (f4 & 3) << 2;
            float4 v = *(const float4*)(g_h + (size_t)(m0 + row) * HDIM + k0 + c4);
            As[row][c4 + 0] = v.x; As[row][c4 + 1] = v.y;
            As[row][c4 + 2] = v.z; As[row][c4 + 3] = v.w;
        }
        {
            int row = tid >> 4;
            int c4  = (tid & 15) << 2;
            *(float4*)&Bs[row][c4] =
                *(const float4*)(Who + (size_t)(k0 + row) * ODIM + c4);
        }
        __syncthreads();
#pragma unroll
        for (int k = 0; k < 16; k++) {
            ulonglong2 bv = *(const ulonglong2*)&Bs[k][tx * 4];
#pragma unroll
            for (int i = 0; i < 8; i++) {
                ull a2 = splat2(As[ty * 8 + i][k]);
                acc[i][0] = ffma2(a2, bv.x, acc[i][0]);
                acc[i][1] = ffma2(a2, bv.y, acc[i][1]);
            }
        }
        __syncthreads();
    }

    float bb0 = bho[tx * 4 + 0], bb1 = bho[tx * 4 + 1];
    float bb2 = bho[tx * 4 + 2], bb3 = bho[tx * 4 + 3];
#pragma unroll
    for (int i = 0; i < 8; i++) {
        float2 v0 = upk2(acc[i][0]); v0.x += bb0; v0.y += bb1;
        float2 v1 = upk2(acc[i][1]); v1.x += bb2; v1.y += bb3;
        float* dst = out + (size_t)(m0 + ty * 8 + i) * ODIM + tx * 4;
        *(float2*)(dst + 0) = v0;
        *(float2*)(dst + 2) = v1;
    }
}

// ============================================================================
extern "C" void kernel_launch(void* const* d_in, const int* in_sizes, int n_in,
                              void* d_out, int out_size)
{
    const float* X   = (const float*)d_in[0];   // [128,1024,256]
    const float* Whh = (const float*)d_in[1];   // [512,512]
    const float* Wih = (const float*)d_in[2];   // [256,512]
    const float* bhh = (const float*)d_in[3];   // [512]
    const float* Who = (const float*)d_in[4];   // [512,64]
    const float* bho = (const float*)d_in[5];   // [64]
    float* out = (float*)d_out;                 // [128,1024,64]

    cudaFuncSetAttribute(rnn_kernel,
                         cudaFuncAttributeMaxDynamicSharedMemorySize,
                         SMEMB_BYTES);

    xproj_kernel<<<dim3(1024, 4, 1), 256>>>(X, Wih, bhh);
    dummy_kernel<<<1, 32>>>();
    dummy_kernel<<<1, 32>>>();
    rnn_kernel<<<128, 256, SMEMB_BYTES>>>(Whh);
    out_kernel<<<1024, 256>>>(Who, bho, out);
}

// round 5
// speedup vs baseline: 1.2094x; 1.1023x over previous
#include <cuda_runtime.h>
#include <cmath>

#define S_LEN  1024
#define BATCHN 128
#define IDIM   256
#define HDIM   512
#define ODIM   64

typedef unsigned long long ull;

// ---------- f32x2 packed helpers ----------
__device__ __forceinline__ ull splat2(float x) {
    ull r; asm("mov.b64 %0, {%1, %1};" : "=l"(r) : "f"(x)); return r;
}
__device__ __forceinline__ ull ffma2(ull a, ull b, ull c) {
    ull d; asm("fma.rn.f32x2 %0, %1, %2, %3;" : "=l"(d) : "l"(a), "l"(b), "l"(c)); return d;
}
__device__ __forceinline__ ull add2(ull a, ull b) {
    ull d; asm("add.rn.f32x2 %0, %1, %2;" : "=l"(d) : "l"(a), "l"(b)); return d;
}
__device__ __forceinline__ float2 upk2(ull v) {
    float2 f; asm("mov.b64 {%0, %1}, %2;" : "=f"(f.x), "=f"(f.y) : "l"(v)); return f;
}
__device__ __forceinline__ unsigned s2u32(const void* p) {
    unsigned a;
    asm("{ .reg .u64 t; cvta.to.shared.u64 t, %1; cvt.u32.u64 %0, t; }" : "=r"(a) : "l"(p));
    return a;
}
__device__ __forceinline__ unsigned mapa_rank(unsigned a, unsigned r) {
    unsigned d; asm("mapa.shared::cluster.u32 %0, %1, %2;" : "=r"(d) : "r"(a), "r"(r));
    return d;
}
// remote smem store with tx-credit to remote mbarrier (async-proxy completion)
__device__ __forceinline__ void st_async_v2(unsigned dst, float x, float y, unsigned mbar) {
    asm volatile(
        "st.async.shared::cluster.mbarrier::complete_tx::bytes.v2.f32 [%0], {%1, %2}, [%3];"
        :: "r"(dst), "f"(x), "f"(y), "r"(mbar) : "memory");
}
__device__ __forceinline__ void mbar_expect_tx(unsigned mbar, unsigned bytes) {
    asm volatile("mbarrier.arrive.expect_tx.shared.b64 _, [%0], %1;"
                 :: "r"(mbar), "r"(bytes) : "memory");
}
__device__ __forceinline__ void mbar_wait_parity(unsigned mbar, unsigned parity) {
    asm volatile(
        "{\n\t"
        ".reg .pred P;\n"
        "LW_%=:\n\t"
        "mbarrier.try_wait.parity.acquire.cta.shared::cta.b64 P, [%0], %1, 0x989680;\n\t"
        "@P bra LD_%=;\n\t"
        "bra LW_%=;\n"
        "LD_%=:\n\t"
        "}"
        :: "r"(mbar), "r"(parity) : "memory");
}

// ---------- scratch (device globals: allocation-free rule) ----------
__device__ float g_xp[(size_t)BATCHN * S_LEN * HDIM];  // X@W_ih + b_hh, [b][s][h]
__device__ float g_h [(size_t)BATCHN * S_LEN * HDIM];  // hidden states,  [b][s][h]

// ============================================================================
// Kernel A: g_xp[M,512] = X[M,256] @ W_ih[256,512] + b_hh, M = 131072
// ============================================================================
__global__ void __launch_bounds__(256, 2) xproj_kernel(
    const float* __restrict__ X, const float* __restrict__ Wih,
    const float* __restrict__ bhh)
{
    __shared__ float As[128][17];
    __shared__ float Bs[16][128];
    const int tid = threadIdx.x;
    const int m0 = blockIdx.x * 128;
    const int n0 = blockIdx.y * 128;
    const int tx = tid & 15, ty = tid >> 4;

    ull acc[8][4];
#pragma unroll
    for (int i = 0; i < 8; i++)
#pragma unroll
        for (int j = 0; j < 4; j++) acc[i][j] = 0ull;

    for (int k0 = 0; k0 < IDIM; k0 += 16) {
#pragma unroll
        for (int i = 0; i < 2; i++) {
            int f4  = tid + i * 256;
            int row = f4 >> 2;
            int c4  = (f4 & 3) << 2;
            float4 v = *(const float4*)(X + (size_t)(m0 + row) * IDIM + k0 + c4);
            As[row][c4 + 0] = v.x; As[row][c4 + 1] = v.y;
            As[row][c4 + 2] = v.z; As[row][c4 + 3] = v.w;
        }
#pragma unroll
        for (int i = 0; i < 2; i++) {
            int f4  = tid + i * 256;
            int row = f4 >> 5;
            int c4  = (f4 & 31) << 2;
            *(float4*)&Bs[row][c4] =
                *(const float4*)(Wih + (size_t)(k0 + row) * HDIM + n0 + c4);
        }
        __syncthreads();
#pragma unroll
        for (int k = 0; k < 16; k++) {
            ulonglong2 bv0 = *(const ulonglong2*)&Bs[k][tx * 4];
            ulonglong2 bv1 = *(const ulonglong2*)&Bs[k][64 + tx * 4];
#pragma unroll
            for (int i = 0; i < 8; i++) {
                ull a2 = splat2(As[ty * 8 + i][k]);
                acc[i][0] = ffma2(a2, bv0.x, acc[i][0]);
                acc[i][1] = ffma2(a2, bv0.y, acc[i][1]);
                acc[i][2] = ffma2(a2, bv1.x, acc[i][2]);
                acc[i][3] = ffma2(a2, bv1.y, acc[i][3]);
            }
        }
        __syncthreads();
    }

#pragma unroll
    for (int i = 0; i < 8; i++) {
        float* dst = g_xp + (size_t)(m0 + ty * 8 + i) * HDIM + n0;
#pragma unroll
        for (int j = 0; j < 4; j++) {
            int n = (j < 2) ? (tx * 4 + j * 2) : (64 + tx * 4 + (j - 2) * 2);
            float2 v = upk2(acc[i][j]);
            v.x += bhh[n0 + n];
            v.y += bhh[n0 + n + 1];
            *(float2*)(dst + n) = v;
        }
    }
}

// empty launch to shift ncu's fixed profiled-launch slot onto rnn_kernel
__global__ void dummy_kernel() {}

// ============================================================================
// Kernel B: serial recurrence.
// 16 clusters x 8 CTAs; rank r owns W_hh cols [64r,64r+64) as ull col-pairs
// in smem; cluster g owns batch rows [8g,8g+8).
// Per step:
//   phase1: warp w, k-chunk [64w,64w+64). Lane covers col-pairs {ls, ls+16}
//           x 4 batches (rg selects 0-3 / 4-7). W: LDS.64 half-warp dup (1wf);
//           h: 2-addr broadcast LDS.128 from pre-splatted hsf (1wf).
//   phase2: reduce over 8 warps (+xp), tanh, STG h to g_h, then st.async
//           compact h-pair to all 8 peers' hx[t&1] with tx-credit to their
//           mbar[t&1]. No cluster.sync. Consumers try_wait parity, splat own
//           k-chunk hx->hsf, light __syncthreads for prt reuse.
// ============================================================================
#define NT 256
// float offsets
#define OFF_HSF 32768                 // ull[512][10]   (40960 B)
#define OFF_HX  43008                 // f32[2][8][512] (32768 B)
#define OFF_PRT 51200                 // ull[8][8][32]  (16384 B)
#define OFF_MB  55296                 // 2 x mbarrier (ull)
#define SMEMB_BYTES ((55296 + 4) * 4)
#define BSTRIDE ((size_t)S_LEN * HDIM)
#define HX_BUF_BYTES (8 * HDIM * 4)   // 16384

__global__ void __launch_bounds__(NT, 1) __cluster_dims__(8, 1, 1)
rnn_kernel(const float* __restrict__ Whh)
{
    extern __shared__ float sm[];
    ull* Wp  = (ull*)sm;               // [k][jp], k stride 32 ull
    ull* hsf = (ull*)(sm + OFF_HSF);   // [k][b] splatted, k stride 10 ull
    ull* prt = (ull*)(sm + OFF_PRT);   // [w][b][jp]

    const int tid  = threadIdx.x;
    const int rank = blockIdx.x & 7;
    const int g    = blockIdx.x >> 3;
    const int c0   = rank * 64;
    const unsigned smb    = s2u32(sm);
    const unsigned mb_loc = smb + OFF_MB * 4;

    if (tid == 0) {
        asm volatile("mbarrier.init.shared.b64 [%0], 1;" :: "r"(mb_loc)     : "memory");
        asm volatile("mbarrier.init.shared.b64 [%0], 1;" :: "r"(mb_loc + 8) : "memory");
        mbar_expect_tx(mb_loc,     16384u);
        mbar_expect_tx(mb_loc + 8, 16384u);
    }

    // Load W_hh slice once as column pairs (128KB)
    for (int i = tid; i < HDIM * 32; i += NT) {
        int k = i >> 5, jp = i & 31;
        *(float2*)(Wp + i) = *(const float2*)(Whh + (size_t)k * HDIM + c0 + 2 * jp);
    }
    // zero hsf (h0 splats) + hx
    for (int i = tid; i < HDIM * 20 + 2 * 8 * HDIM; i += NT) sm[OFF_HSF + i] = 0.f;
    __syncthreads();
    asm volatile("barrier.cluster.arrive.aligned;" ::: "memory");
    asm volatile("barrier.cluster.wait.aligned;"   ::: "memory");

    const int w  = tid >> 5, l = tid & 31;
    const int rg = l >> 4,  ls = l & 15;
    const int kbeg = w * 64;

    // phase-1 pointers
    const ull* wsp = Wp  + (size_t)kbeg * 32 + ls;      // wsp[k*32], wsp[k*32+16]
    const ull* hsp = hsf + (size_t)kbeg * 10 + rg * 4;  // batches rg*4.. at +k*10
    ull*       pw  = prt + w * 256 + (rg * 4) * 32;     // + q*32 + ls (+16)

    // phase-2 mapping: warp -> batch b=w, lane -> col pair jp=l
    const ull* pr = prt + w * 32 + l;
    const float* xpp = g_xp + ((size_t)(g * 8 + w)) * BSTRIDE + c0 + 2 * l;
    float*       ghw = g_h  + ((size_t)(g * 8 + w)) * BSTRIDE + c0 + 2 * l;

    // push targets: peer r's hx[0][b=w][c0+2l] and peer r's mbar[0]
    const unsigned hx_loc = smb + (unsigned)((OFF_HX + w * HDIM + c0 + 2 * l) * 4);
    unsigned peer[8], peer_mb[8];
#pragma unroll
    for (int r = 0; r < 8; r++) {
        peer[r]    = mapa_rank(hx_loc, (unsigned)r);
        peer_mb[r] = mapa_rank(mb_loc, (unsigned)r);
    }

    // splat-pass pointers: warp w covers k = kbeg+l and kbeg+32+l, all 8 b
    const float* spl_src = sm + OFF_HX + kbeg + l;        // + buf*4096 + b*512 (+32)
    ull*         spl_dst = hsf + (size_t)(kbeg + l) * 10; // + b ; k+32 -> +320

    for (int t = 0; t < S_LEN; t++) {
        // prefetch xp pair (consumed after phase 1)
        ull xv = *(const ull*)(xpp + (size_t)t * HDIM);

        // ---- phase 1: 2 col-pairs x 4 batches per lane ----
        ull a00 = 0, a01 = 0, a02 = 0, a03 = 0;
        ull a10 = 0, a11 = 0, a12 = 0, a13 = 0;
#pragma unroll 2
        for (int k = 0; k < 64; k++) {
            ull w0 = wsp[k * 32];
            ull w1 = wsp[k * 32 + 16];
            ulonglong2 hlo = *(const ulonglong2*)(hsp + k * 10);      // b rg*4+0,1
            ulonglong2 hhi = *(const ulonglong2*)(hsp + k * 10 + 2);  // b rg*4+2,3
            a00 = ffma2(w0, hlo.x, a00);
            a01 = ffma2(w0, hlo.y, a01);
            a02 = ffma2(w0, hhi.x, a02);
            a03 = ffma2(w0, hhi.y, a03);
            a10 = ffma2(w1, hlo.x, a10);
            a11 = ffma2(w1, hlo.y, a11);
            a12 = ffma2(w1, hhi.x, a12);
            a13 = ffma2(w1, hhi.y, a13);
        }
        pw[0 * 32 + ls]      = a00;
        pw[1 * 32 + ls]      = a01;
        pw[2 * 32 + ls]      = a02;
        pw[3 * 32 + ls]      = a03;
        pw[0 * 32 + ls + 16] = a10;
        pw[1 * 32 + ls + 16] = a11;
        pw[2 * 32 + ls + 16] = a12;
        pw[3 * 32 + ls + 16] = a13;
        __syncthreads();

        // ---- phase 2: reduce + tanh + publish ----
        ull s = xv;
        s = add2(s, pr[0]);    s = add2(s, pr[256]);
        s = add2(s, pr[512]);  s = add2(s, pr[768]);
        s = add2(s, pr[1024]); s = add2(s, pr[1280]);
        s = add2(s, pr[1536]); s = add2(s, pr[1792]);
        float2 sv = upk2(s);
        float h0 = tanhf(sv.x);
        float h1 = tanhf(sv.y);
        *(float2*)(ghw + (size_t)t * HDIM) = make_float2(h0, h1);

        if (t == S_LEN - 1) break;   // nobody needs h(S); no in-flight DSMEM at exit

        const unsigned hxo = (unsigned)((t & 1) * HX_BUF_BYTES);
        const unsigned mbo = (unsigned)((t & 1) * 8);
#pragma unroll
        for (int r = 0; r < 8; r++)
            st_async_v2(peer[r] + hxo, h0, h1, peer_mb[r] + mbo);

        // ---- wait for all 16KB inbound, then splat own k-chunk ----
        mbar_wait_parity(mb_loc + mbo, (unsigned)((t >> 1) & 1));
        if (tid == 0) mbar_expect_tx(mb_loc + mbo, 16384u);  // re-arm next phase
        {
            const float* src = spl_src + (t & 1) * (8 * HDIM);
#pragma unroll
            for (int b = 0; b < 8; b++) {
                float f0 = src[b * HDIM];
                float f1 = src[b * HDIM + 32];
                spl_dst[b]       = splat2(f0);
                spl_dst[320 + b] = splat2(f1);
            }
        }
        __syncthreads();   // protect prt reuse (warps/CTAs now decoupled)
    }
}

// ============================================================================
// Kernel C: out[M,64] = g_h[M,512] @ W_ho[512,64] + b_ho, M = 131072
// ============================================================================
__global__ void __launch_bounds__(256) out_kernel(
    const float* __restrict__ Who, const float* __restrict__ bho,
    float* __restrict__ out)
{
    __shared__ float As[128][17];
    __shared__ float Bs[16][64];
    const int tid = threadIdx.x;
    const int m0 = blockIdx.x * 128;
    const int tx = tid & 15, ty = tid >> 4;

    ull acc[8][2];
#pragma unroll
    for (int i = 0; i < 8; i++) { acc[i][0] = 0ull; acc[i][1] = 0ull; }

    for (int k0 = 0; k0 < HDIM; k0 += 16) {
#pragma unroll
        for (int i = 0; i < 2; i++) {
            int f4  = tid + i * 256;
            int row = f4 >> 2;
            int c4  = (f4 & 3) << 2;
            float4 v = *(const float4*)(g_h + (size_t)(m0 + row) * HDIM + k0 + c4);
            As[row][c4 + 0] = v.x; As[row][c4 + 1] = v.y;
            As[row][c4 + 2] = v.z; As[row][c4 + 3] = v.w;
        }
        {
            int row = tid >> 4;
            int c4  = (tid & 15) << 2;
            *(float4*)&Bs[row][c4] =
                *(const float4*)(Who + (size_t)(k0 + row) * ODIM + c4);
        }
        __syncthreads();
#pragma unroll
        for (int k = 0; k < 16; k++) {
            ulonglong2 bv = *(const ulonglong2*)&Bs[k][tx * 4];
#pragma unroll
            for (int i = 0; i < 8; i++) {
                ull a2 = splat2(As[ty * 8 + i][k]);
                acc[i][0] = ffma2(a2, bv.x, acc[i][0]);
                acc[i][1] = ffma2(a2, bv.y, acc[i][1]);
            }
        }
        __syncthreads();
    }

    float bb0 = bho[tx * 4 + 0], bb1 = bho[tx * 4 + 1];
    float bb2 = bho[tx * 4 + 2], bb3 = bho[tx * 4 + 3];
#pragma unroll
    for (int i = 0; i < 8; i++) {
        float2 v0 = upk2(acc[i][0]); v0.x += bb0; v0.y += bb1;
        float2 v1 = upk2(acc[i][1]); v1.x += bb2; v1.y += bb3;
        float* dst = out + (size_t)(m0 + ty * 8 + i) * ODIM + tx * 4;
        *(float2*)(dst + 0) = v0;
        *(float2*)(dst + 2) = v1;
    }
}

// ============================================================================
extern "C" void kernel_launch(void* const* d_in, const int* in_sizes, int n_in,
                              void* d_out, int out_size)
{
    const float* X   = (const float*)d_in[0];   // [128,1024,256]
    const float* Whh = (const float*)d_in[1];   // [512,512]
    const float* Wih = (const float*)d_in[2];   // [256,512]
    const float* bhh = (const float*)d_in[3];   // [512]
    const float* Who = (const float*)d_in[4];   // [512,64]
    const float* bho = (const float*)d_in[5];   // [64]
    float* out = (float*)d_out;                 // [128,1024,64]

    cudaFuncSetAttribute(rnn_kernel,
                         cudaFuncAttributeMaxDynamicSharedMemorySize,
                         SMEMB_BYTES);

    xproj_kernel<<<dim3(1024, 4, 1), 256>>>(X, Wih, bhh);
    dummy_kernel<<<1, 32>>>();
    dummy_kernel<<<1, 32>>>();
    rnn_kernel<<<128, 256, SMEMB_BYTES>>>(Whh);
    out_kernel<<<1024, 256>>>(Who, bho, out);
}

// round 6
// speedup vs baseline: 1.2287x; 1.0160x over previous
#include <cuda_runtime.h>
#include <cmath>

#define S_LEN  1024
#define BATCHN 128
#define IDIM   256
#define HDIM   512
#define ODIM   64

typedef unsigned long long ull;

// ---------- f32x2 packed helpers ----------
__device__ __forceinline__ ull splat2(float x) {
    ull r; asm("mov.b64 %0, {%1, %1};" : "=l"(r) : "f"(x)); return r;
}
__device__ __forceinline__ ull ffma2(ull a, ull b, ull c) {
    ull d; asm("fma.rn.f32x2 %0, %1, %2, %3;" : "=l"(d) : "l"(a), "l"(b), "l"(c)); return d;
}
__device__ __forceinline__ ull add2(ull a, ull b) {
    ull d; asm("add.rn.f32x2 %0, %1, %2;" : "=l"(d) : "l"(a), "l"(b)); return d;
}
__device__ __forceinline__ float2 upk2(ull v) {
    float2 f; asm("mov.b64 {%0, %1}, %2;" : "=f"(f.x), "=f"(f.y) : "l"(v)); return f;
}
__device__ __forceinline__ unsigned s2u32(const void* p) {
    unsigned a;
    asm("{ .reg .u64 t; cvta.to.shared.u64 t, %1; cvt.u32.u64 %0, t; }" : "=r"(a) : "l"(p));
    return a;
}
__device__ __forceinline__ unsigned mapa_rank(unsigned a, unsigned r) {
    unsigned d; asm("mapa.shared::cluster.u32 %0, %1, %2;" : "=r"(d) : "r"(a), "r"(r));
    return d;
}
// bulk smem->peer-smem copy with tx-credit to the peer's mbarrier
__device__ __forceinline__ void bulk_s2c(unsigned dst, unsigned src, unsigned bytes,
                                         unsigned mbar) {
    asm volatile(
        "cp.async.bulk.shared::cluster.shared::cta.mbarrier::complete_tx::bytes "
        "[%0], [%1], %2, [%3];"
        :: "r"(dst), "r"(src), "r"(bytes), "r"(mbar) : "memory");
}
__device__ __forceinline__ void mbar_expect_tx(unsigned mbar, unsigned bytes) {
    asm volatile("mbarrier.arrive.expect_tx.shared.b64 _, [%0], %1;"
                 :: "r"(mbar), "r"(bytes) : "memory");
}
__device__ __forceinline__ void mbar_wait_parity(unsigned mbar, unsigned parity) {
    asm volatile(
        "{\n\t"
        ".reg .pred P;\n"
        "LW_%=:\n\t"
        "mbarrier.try_wait.parity.acquire.cta.shared::cta.b64 P, [%0], %1, 0x989680;\n\t"
        "@P bra LD_%=;\n\t"
        "bra LW_%=;\n"
        "LD_%=:\n\t"
        "}"
        :: "r"(mbar), "r"(parity) : "memory");
}

// ---------- scratch (device globals: allocation-free rule) ----------
__device__ float g_xp[(size_t)BATCHN * S_LEN * HDIM];  // X@W_ih + b_hh, [b][s][h]
__device__ float g_h [(size_t)BATCHN * S_LEN * HDIM];  // hidden states,  [b][s][h]

// ============================================================================
// Kernel A: g_xp[M,512] = X[M,256] @ W_ih[256,512] + b_hh, M = 131072
// ============================================================================
__global__ void __launch_bounds__(256, 2) xproj_kernel(
    const float* __restrict__ X, const float* __restrict__ Wih,
    const float* __restrict__ bhh)
{
    __shared__ float As[128][17];
    __shared__ float Bs[16][128];
    const int tid = threadIdx.x;
    const int m0 = blockIdx.x * 128;
    const int n0 = blockIdx.y * 128;
    const int tx = tid & 15, ty = tid >> 4;

    ull acc[8][4];
#pragma unroll
    for (int i = 0; i < 8; i++)
#pragma unroll
        for (int j = 0; j < 4; j++) acc[i][j] = 0ull;

    for (int k0 = 0; k0 < IDIM; k0 += 16) {
#pragma unroll
        for (int i = 0; i < 2; i++) {
            int f4  = tid + i * 256;
            int row = f4 >> 2;
            int c4  = (f4 & 3) << 2;
            float4 v = *(const float4*)(X + (size_t)(m0 + row) * IDIM + k0 + c4);
            As[row][c4 + 0] = v.x; As[row][c4 + 1] = v.y;
            As[row][c4 + 2] = v.z; As[row][c4 + 3] = v.w;
        }
#pragma unroll
        for (int i = 0; i < 2; i++) {
            int f4  = tid + i * 256;
            int row = f4 >> 5;
            int c4  = (f4 & 31) << 2;
            *(float4*)&Bs[row][c4] =
                *(const float4*)(Wih + (size_t)(k0 + row) * HDIM + n0 + c4);
        }
        __syncthreads();
#pragma unroll
        for (int k = 0; k < 16; k++) {
            ulonglong2 bv0 = *(const ulonglong2*)&Bs[k][tx * 4];
            ulonglong2 bv1 = *(const ulonglong2*)&Bs[k][64 + tx * 4];
#pragma unroll
            for (int i = 0; i < 8; i++) {
                ull a2 = splat2(As[ty * 8 + i][k]);
                acc[i][0] = ffma2(a2, bv0.x, acc[i][0]);
                acc[i][1] = ffma2(a2, bv0.y, acc[i][1]);
                acc[i][2] = ffma2(a2, bv1.x, acc[i][2]);
                acc[i][3] = ffma2(a2, bv1.y, acc[i][3]);
            }
        }
        __syncthreads();
    }

#pragma unroll
    for (int i = 0; i < 8; i++) {
        float* dst = g_xp + (size_t)(m0 + ty * 8 + i) * HDIM + n0;
#pragma unroll
        for (int j = 0; j < 4; j++) {
            int n = (j < 2) ? (tx * 4 + j * 2) : (64 + tx * 4 + (j - 2) * 2);
            float2 v = upk2(acc[i][j]);
            v.x += bhh[n0 + n];
            v.y += bhh[n0 + n + 1];
            *(float2*)(dst + n) = v;
        }
    }
}

// empty launch to shift ncu's fixed profiled-launch slot onto rnn_kernel
__global__ void dummy_kernel() {}

// ============================================================================
// Kernel B: serial recurrence.
// 16 clusters x 8 CTAs; rank r owns W_hh cols [64r,64r+64) as ull col-pairs
// in smem; cluster g owns batch rows [8g,8g+8).
// Per step:
//   phase1: warp w, k-chunk [64w,64w+64): col-pairs {ls,ls+16} x 4 batches.
//   phase2: reduce over 8 warps (+xp), tanh, STG to g_h, STS h-slice into
//           contiguous stg[buf] (2KB), __syncthreads, then threads 0-7 each
//           issue ONE cp.async.bulk (2KB) to peer r's hx[buf][rank] with
//           complete_tx to peer's mbar[buf] (expect 16KB). try_wait parity,
//           splat own inbound block hx[buf][w] -> hsf. No cluster.sync.
// ============================================================================
#define NT 256
// float offsets
#define OFF_HSF 32768                  // ull[512][10]        (40960 B)
#define OFF_HX  43008                  // f32[2][8][8][64]    (32768 B)
#define OFF_PRT 51200                  // ull[8][8][32]       (16384 B)
#define OFF_STG 55296                  // f32[2][512]         (4096 B)
#define OFF_MB  56320                  // 2 x mbarrier (ull)
#define SMEMB_BYTES ((56320 + 4) * 4)
#define BSTRIDE ((size_t)S_LEN * HDIM)
#define HX_BUF_BYTES  16384u           // one hx buffer: 8 ranks x 2KB
#define BLK_BYTES     2048u            // one rank's block (8 b x 64 cols x 4B)

__global__ void __launch_bounds__(NT, 1) __cluster_dims__(8, 1, 1)
rnn_kernel(const float* __restrict__ Whh)
{
    extern __shared__ float sm[];
    ull* Wp  = (ull*)sm;               // [k][jp], k stride 32 ull
    ull* hsf = (ull*)(sm + OFF_HSF);   // [k][b] splatted, k stride 10 ull
    ull* prt = (ull*)(sm + OFF_PRT);   // [w][b][jp]

    const int tid  = threadIdx.x;
    const int rank = blockIdx.x & 7;
    const int g    = blockIdx.x >> 3;
    const int c0   = rank * 64;
    const unsigned smb    = s2u32(sm);
    const unsigned mb_loc = smb + OFF_MB * 4;
    const unsigned stg_b  = smb + OFF_STG * 4;

    if (tid == 0) {
        asm volatile("mbarrier.init.shared.b64 [%0], 1;" :: "r"(mb_loc)     : "memory");
        asm volatile("mbarrier.init.shared.b64 [%0], 1;" :: "r"(mb_loc + 8) : "memory");
        mbar_expect_tx(mb_loc,     HX_BUF_BYTES);
        mbar_expect_tx(mb_loc + 8, HX_BUF_BYTES);
    }

    // Load W_hh slice once as column pairs (128KB)
    for (int i = tid; i < HDIM * 32; i += NT) {
        int k = i >> 5, jp = i & 31;
        *(float2*)(Wp + i) = *(const float2*)(Whh + (size_t)k * HDIM + c0 + 2 * jp);
    }
    // zero hsf (h0 splats) + hx
    for (int i = tid; i < HDIM * 20 + 2 * 8 * HDIM; i += NT) sm[OFF_HSF + i] = 0.f;
    __syncthreads();
    asm volatile("barrier.cluster.arrive.aligned;" ::: "memory");
    asm volatile("barrier.cluster.wait.aligned;"   ::: "memory");

    const int w  = tid >> 5, l = tid & 31;
    const int rg = l >> 4,  ls = l & 15;
    const int kbeg = w * 64;

    // phase-1 pointers
    const ull* wsp = Wp  + (size_t)kbeg * 32 + ls;      // wsp[k*32], wsp[k*32+16]
    const ull* hsp = hsf + (size_t)kbeg * 10 + rg * 4;  // batches rg*4.. at +k*10
    ull*       pw  = prt + w * 256 + (rg * 4) * 32;     // + q*32 + ls (+16)

    // phase-2 mapping: warp -> batch b=w, lane -> col pair jp=l
    const ull* pr = prt + w * 32 + l;
    const float* xpp = g_xp + ((size_t)(g * 8 + w)) * BSTRIDE + c0 + 2 * l;
    float*       ghw = g_h  + ((size_t)(g * 8 + w)) * BSTRIDE + c0 + 2 * l;
    float*       stw = sm + OFF_STG + w * 64 + 2 * l;   // + buf*512

    // bulk targets: peer r's hx[0][rank] block and peer r's mbar[0]
    unsigned peer_hx[8], peer_mb[8];
    {
        const unsigned hx0 = smb + OFF_HX * 4 + (unsigned)rank * BLK_BYTES;
#pragma unroll
        for (int r = 0; r < 8; r++) {
            peer_hx[r] = mapa_rank(hx0, (unsigned)r);
            peer_mb[r] = mapa_rank(mb_loc, (unsigned)r);
        }
    }

    // splat-pass pointers: warp w consumes inbound block from srcRank w
    // hx[buf][w][b][ko], lane handles ko = l and l+32 for all 8 b
    const float* spl_src = sm + OFF_HX + w * 512 + l;      // + buf*4096 + b*64 (+32)
    ull*         spl_dst = hsf + (size_t)(kbeg + l) * 10;  // + b ; k+32 -> +320

    for (int t = 0; t < S_LEN; t++) {
        // prefetch xp pair (consumed after phase 1)
        ull xv = *(const ull*)(xpp + (size_t)t * HDIM);

        // ---- phase 1: 2 col-pairs x 4 batches per lane ----
        ull a00 = 0, a01 = 0, a02 = 0, a03 = 0;
        ull a10 = 0, a11 = 0, a12 = 0, a13 = 0;
#pragma unroll 4
        for (int k = 0; k < 64; k++) {
            ull w0 = wsp[k * 32];
            ull w1 = wsp[k * 32 + 16];
            ulonglong2 hlo = *(const ulonglong2*)(hsp + k * 10);      // b rg*4+0,1
            ulonglong2 hhi = *(const ulonglong2*)(hsp + k * 10 + 2);  // b rg*4+2,3
            a00 = ffma2(w0, hlo.x, a00);
            a01 = ffma2(w0, hlo.y, a01);
            a02 = ffma2(w0, hhi.x, a02);
            a03 = ffma2(w0, hhi.y, a03);
            a10 = ffma2(w1, hlo.x, a10);
            a11 = ffma2(w1, hlo.y, a11);
            a12 = ffma2(w1, hhi.x, a12);
            a13 = ffma2(w1, hhi.y, a13);
        }
        pw[0 * 32 + ls]      = a00;
        pw[1 * 32 + ls]      = a01;
        pw[2 * 32 + ls]      = a02;
        pw[3 * 32 + ls]      = a03;
        pw[0 * 32 + ls + 16] = a10;
        pw[1 * 32 + ls + 16] = a11;
        pw[2 * 32 + ls + 16] = a12;
        pw[3 * 32 + ls + 16] = a13;
        __syncthreads();

        // ---- phase 2: reduce + tanh ----
        ull s = xv;
        s = add2(s, pr[0]);    s = add2(s, pr[256]);
        s = add2(s, pr[512]);  s = add2(s, pr[768]);
        s = add2(s, pr[1024]); s = add2(s, pr[1280]);
        s = add2(s, pr[1536]); s = add2(s, pr[1792]);
        float2 sv = upk2(s);
        float h0 = tanhf(sv.x);
        float h1 = tanhf(sv.y);
        *(float2*)(ghw + (size_t)t * HDIM) = make_float2(h0, h1);

        if (t == S_LEN - 1) break;   // nobody needs h(S); no in-flight traffic at exit

        const int buf = t & 1;
        *(float2*)(stw + buf * 512) = make_float2(h0, h1);   // stage own slice
        __syncthreads();   // stg complete + prt reads done (safe reuse next iter)

        if (tid < 8) {
            asm volatile("fence.proxy.async.shared::cta;" ::: "memory");
            bulk_s2c(peer_hx[tid] + (unsigned)buf * HX_BUF_BYTES,
                     stg_b + (unsigned)buf * BLK_BYTES,
                     BLK_BYTES,
                     peer_mb[tid] + (unsigned)buf * 8);
        }

        // ---- wait for all 16KB inbound, then splat own block ----
        const unsigned mbo = (unsigned)(buf * 8);
        mbar_wait_parity(mb_loc + mbo, (unsigned)((t >> 1) & 1));
        if (tid == 0) mbar_expect_tx(mb_loc + mbo, HX_BUF_BYTES);  // re-arm
        {
            const float* src = spl_src + buf * 4096;
#pragma unroll
            for (int b = 0; b < 8; b++) {
                float f0 = src[b * 64];
                float f1 = src[b * 64 + 32];
                spl_dst[b]       = splat2(f0);
                spl_dst[320 + b] = splat2(f1);
            }
        }
    }
}

// ============================================================================
// Kernel C: out[M,64] = g_h[M,512] @ W_ho[512,64] + b_ho, M = 131072
// ============================================================================
__global__ void __launch_bounds__(256) out_kernel(
    const float* __restrict__ Who, const float* __restrict__ bho,
    float* __restrict__ out)
{
    __shared__ float As[128][17];
    __shared__ float Bs[16][64];
    const int tid = threadIdx.x;
    const int m0 = blockIdx.x * 128;
    const int tx = tid & 15, ty = tid >> 4;

    ull acc[8][2];
#pragma unroll
    for (int i = 0; i < 8; i++) { acc[i][0] = 0ull; acc[i][1] = 0ull; }

    for (int k0 = 0; k0 < HDIM; k0 += 16) {
#pragma unroll
        for (int i = 0; i < 2; i++) {
            int f4  = tid + i * 256;
            int row = f4 >> 2;
            int c4  = (f4 & 3) << 2;
            float4 v = *(const float4*)(g_h + (size_t)(m0 + row) * HDIM + k0 + c4);
            As[row][c4 + 0] = v.x; As[row][c4 + 1] = v.y;
            As[row][c4 + 2] = v.z; As[row][c4 + 3] = v.w;
        }
        {
            int row = tid >> 4;
            int c4  = (tid & 15) << 2;
            *(float4*)&Bs[row][c4] =
                *(const float4*)(Who + (size_t)(k0 + row) * ODIM + c4);
        }
        __syncthreads();
#pragma unroll
        for (int k = 0; k < 16; k++) {
            ulonglong2 bv = *(const ulonglong2*)&Bs[k][tx * 4];
#pragma unroll
            for (int i = 0; i < 8; i++) {
                ull a2 = splat2(As[ty * 8 + i][k]);
                acc[i][0] = ffma2(a2, bv.x, acc[i][0]);
                acc[i][1] = ffma2(a2, bv.y, acc[i][1]);
            }
        }
        __syncthreads();
    }

    float bb0 = bho[tx * 4 + 0], bb1 = bho[tx * 4 + 1];
    float bb2 = bho[tx * 4 + 2], bb3 = bho[tx * 4 + 3];
#pragma unroll
    for (int i = 0; i < 8; i++) {
        float2 v0 = upk2(acc[i][0]); v0.x += bb0; v0.y += bb1;
        float2 v1 = upk2(acc[i][1]); v1.x += bb2; v1.y += bb3;
        float* dst = out + (size_t)(m0 + ty * 8 + i) * ODIM + tx * 4;
        *(float2*)(dst + 0) = v0;
        *(float2*)(dst + 2) = v1;
    }
}

// ============================================================================
extern "C" void kernel_launch(void* const* d_in, const int* in_sizes, int n_in,
                              void* d_out, int out_size)
{
    const float* X   = (const float*)d_in[0];   // [128,1024,256]
    const float* Whh = (const float*)d_in[1];   // [512,512]
    const float* Wih = (const float*)d_in[2];   // [256,512]
    const float* bhh = (const float*)d_in[3];   // [512]
    const float* Who = (const float*)d_in[4];   // [512,64]
    const float* bho = (const float*)d_in[5];   // [64]
    float* out = (float*)d_out;                 // [128,1024,64]

    cudaFuncSetAttribute(rnn_kernel,
                         cudaFuncAttributeMaxDynamicSharedMemorySize,
                         SMEMB_BYTES);

    xproj_kernel<<<dim3(1024, 4, 1), 256>>>(X, Wih, bhh);
    dummy_kernel<<<1, 32>>>();
    dummy_kernel<<<1, 32>>>();
    rnn_kernel<<<128, 256, SMEMB_BYTES>>>(Whh);
    out_kernel<<<1024, 256>>>(Who, bho, out);
}

// round 7
// speedup vs baseline: 1.4994x; 1.2203x over previous
#include <cuda_runtime.h>
#include <cmath>

#define S_LEN  1024
#define BATCHN 128
#define IDIM   256
#define HDIM   512
#define ODIM   64

typedef unsigned long long ull;

// ---------- f32x2 packed helpers ----------
__device__ __forceinline__ ull splat2(float x) {
    ull r; asm("mov.b64 %0, {%1, %1};" : "=l"(r) : "f"(x)); return r;
}
__device__ __forceinline__ ull ffma2(ull a, ull b, ull c) {
    ull d; asm("fma.rn.f32x2 %0, %1, %2, %3;" : "=l"(d) : "l"(a), "l"(b), "l"(c)); return d;
}
__device__ __forceinline__ ull add2(ull a, ull b) {
    ull d; asm("add.rn.f32x2 %0, %1, %2;" : "=l"(d) : "l"(a), "l"(b)); return d;
}
__device__ __forceinline__ float2 upk2(ull v) {
    float2 f; asm("mov.b64 {%0, %1}, %2;" : "=f"(f.x), "=f"(f.y) : "l"(v)); return f;
}
__device__ __forceinline__ unsigned s2u32(const void* p) {
    unsigned a;
    asm("{ .reg .u64 t; cvta.to.shared.u64 t, %1; cvt.u32.u64 %0, t; }" : "=r"(a) : "l"(p));
    return a;
}
__device__ __forceinline__ unsigned mapa_rank(unsigned a, unsigned r) {
    unsigned d; asm("mapa.shared::cluster.u32 %0, %1, %2;" : "=r"(d) : "r"(a), "r"(r));
    return d;
}
__device__ __forceinline__ void bulk_s2c(unsigned dst, unsigned src, unsigned bytes,
                                         unsigned mbar) {
    asm volatile(
        "cp.async.bulk.shared::cluster.shared::cta.mbarrier::complete_tx::bytes "
        "[%0], [%1], %2, [%3];"
        :: "r"(dst), "r"(src), "r"(bytes), "r"(mbar) : "memory");
}
__device__ __forceinline__ void mbar_expect_tx(unsigned mbar, unsigned bytes) {
    asm volatile("mbarrier.arrive.expect_tx.shared.b64 _, [%0], %1;"
                 :: "r"(mbar), "r"(bytes) : "memory");
}
__device__ __forceinline__ void mbar_wait_parity(unsigned mbar, unsigned parity) {
    asm volatile(
        "{\n\t"
        ".reg .pred P;\n"
        "LW_%=:\n\t"
        "mbarrier.try_wait.parity.acquire.cta.shared::cta.b64 P, [%0], %1, 0x989680;\n\t"
        "@P bra LD_%=;\n\t"
        "bra LW_%=;\n"
        "LD_%=:\n\t"
        "}"
        :: "r"(mbar), "r"(parity) : "memory");
}

// ---------- scratch (device globals: allocation-free rule) ----------
__device__ float g_xp[(size_t)BATCHN * S_LEN * HDIM];  // X@W_ih + b_hh, [b][s][h]
__device__ float g_h [(size_t)BATCHN * S_LEN * HDIM];  // hidden states,  [b][s][h]

// ============================================================================
// Kernel A: g_xp[M,512] = X[M,256] @ W_ih[256,512] + b_hh, M = 131072
// ============================================================================
__global__ void __launch_bounds__(256, 2) xproj_kernel(
    const float* __restrict__ X, const float* __restrict__ Wih,
    const float* __restrict__ bhh)
{
    __shared__ float As[128][17];
    __shared__ float Bs[16][128];
    const int tid = threadIdx.x;
    const int m0 = blockIdx.x * 128;
    const int n0 = blockIdx.y * 128;
    const int tx = tid & 15, ty = tid >> 4;

    ull acc[8][4];
#pragma unroll
    for (int i = 0; i < 8; i++)
#pragma unroll
        for (int j = 0; j < 4; j++) acc[i][j] = 0ull;

    for (int k0 = 0; k0 < IDIM; k0 += 16) {
#pragma unroll
        for (int i = 0; i < 2; i++) {
            int f4  = tid + i * 256;
            int row = f4 >> 2;
            int c4  = (f4 & 3) << 2;
            float4 v = *(const float4*)(X + (size_t)(m0 + row) * IDIM + k0 + c4);
            As[row][c4 + 0] = v.x; As[row][c4 + 1] = v.y;
            As[row][c4 + 2] = v.z; As[row][c4 + 3] = v.w;
        }
#pragma unroll
        for (int i = 0; i < 2; i++) {
            int f4  = tid + i * 256;
            int row = f4 >> 5;
            int c4  = (f4 & 31) << 2;
            *(float4*)&Bs[row][c4] =
                *(const float4*)(Wih + (size_t)(k0 + row) * HDIM + n0 + c4);
        }
        __syncthreads();
#pragma unroll
        for (int k = 0; k < 16; k++) {
            ulonglong2 bv0 = *(const ulonglong2*)&Bs[k][tx * 4];
            ulonglong2 bv1 = *(const ulonglong2*)&Bs[k][64 + tx * 4];
#pragma unroll
            for (int i = 0; i < 8; i++) {
                ull a2 = splat2(As[ty * 8 + i][k]);
                acc[i][0] = ffma2(a2, bv0.x, acc[i][0]);
                acc[i][1] = ffma2(a2, bv0.y, acc[i][1]);
                acc[i][2] = ffma2(a2, bv1.x, acc[i][2]);
                acc[i][3] = ffma2(a2, bv1.y, acc[i][3]);
            }
        }
        __syncthreads();
    }

#pragma unroll
    for (int i = 0; i < 8; i++) {
        float* dst = g_xp + (size_t)(m0 + ty * 8 + i) * HDIM + n0;
#pragma unroll
        for (int j = 0; j < 4; j++) {
            int n = (j < 2) ? (tx * 4 + j * 2) : (64 + tx * 4 + (j - 2) * 2);
            float2 v = upk2(acc[i][j]);
            v.x += bhh[n0 + n];
            v.y += bhh[n0 + n + 1];
            *(float2*)(dst + n) = v;
        }
    }
}

// empty launch to shift ncu's fixed profiled-launch slot onto rnn_kernel
__global__ void dummy_kernel() {}

// ============================================================================
// Kernel B: serial recurrence. 16 clusters x 8 CTAs; rank r owns W_hh cols
// [64r,64r+64) as ull col-pairs in smem; cluster g owns batch rows [8g,8g+8).
// 512 threads (16 warps, 4/SMSP) for latency hiding.
//
// hx exchange buffer layout (per buf, per srcRank block of 2KB):
//   hx[buf][src][grp][kLocal][bi]  floats, grp=b>>2 (2), kLocal (64), bi=b&3 (4)
// Phase-1 reads h directly from hx: 1 broadcast LDS.128 = 4 batches at one k.
//
// Per step:
//   phase1: warp w, k-chunk [32w, 32w+32): col-pairs {ls,ls+16} x 4 batches
//           (rg). Partials -> prt[16][8][32].
//   phase2 (warps 0-7, b=w): reduce 16 partials (+xp), tanh, STG to g_h,
//           STS into own hx[buf][rank] block; sync; threads 0-7 (!=rank)
//           bulk-copy own 2KB block to peers with complete_tx (expect 14KB);
//           all warps try_wait parity. No cluster.sync, no splat pass.
// ============================================================================
#define NT 512
// float offsets: Wp ull[512][32] | prt ull[16][8][32] | hx f32[2][8][512] | mb
#define OFF_PRT 32768
#define OFF_HX  40960
#define OFF_MB  49152
#define SMEMB_BYTES ((49152 + 4) * 4)
#define BSTRIDE ((size_t)S_LEN * HDIM)
#define BLK_BYTES   2048u              // one src-rank block
#define EXPECT_TX   (7u * BLK_BYTES)   // 7 peers (self via STS)

__global__ void __launch_bounds__(NT, 1) __cluster_dims__(8, 1, 1)
rnn_kernel(const float* __restrict__ Whh)
{
    extern __shared__ float sm[];
    ull* Wp  = (ull*)sm;               // [k][jp], k stride 32 ull
    ull* prt = (ull*)(sm + OFF_PRT);   // [w16][b][jp]

    const int tid  = threadIdx.x;
    const int rank = blockIdx.x & 7;
    const int g    = blockIdx.x >> 3;
    const int c0   = rank * 64;
    const unsigned smb    = s2u32(sm);
    const unsigned mb_loc = smb + OFF_MB * 4;

    if (tid == 0) {
        asm volatile("mbarrier.init.shared.b64 [%0], 1;" :: "r"(mb_loc)     : "memory");
        asm volatile("mbarrier.init.shared.b64 [%0], 1;" :: "r"(mb_loc + 8) : "memory");
        mbar_expect_tx(mb_loc,     EXPECT_TX);
        mbar_expect_tx(mb_loc + 8, EXPECT_TX);
    }

    // Load W_hh slice once as column pairs (128KB)
    for (int i = tid; i < HDIM * 32; i += NT) {
        int k = i >> 5, jp = i & 31;
        *(float2*)(Wp + i) = *(const float2*)(Whh + (size_t)k * HDIM + c0 + 2 * jp);
    }
    // zero hx (h0 = 0), both buffers
    for (int i = tid; i < 2 * 8 * HDIM; i += NT) sm[OFF_HX + i] = 0.f;
    __syncthreads();
    asm volatile("barrier.cluster.arrive.aligned;" ::: "memory");
    asm volatile("barrier.cluster.wait.aligned;"   ::: "memory");

    const int w  = tid >> 5, l = tid & 31;
    const int rg = l >> 4,  ls = l & 15;
    const int kbeg = w * 32;

    // phase-1 pointers
    const ull*   wsp = Wp + (size_t)kbeg * 32 + ls;   // wsp[k*32], wsp[k*32+16]
    // h base inside hx buffer: src=w>>1 block, grp=rg, half=(w&1)*32 kLocals
    const float* hxb = sm + OFF_HX + (w >> 1) * 512 + rg * 256 + (w & 1) * 128;
    ull*         pw  = prt + w * 256 + (rg * 4) * 32; // + q*32 + ls (+16)

    // phase-2 mapping (warps 0-7): b = w, lane l = col-pair jp
    const ull* pr = prt + w * 32 + l;
    const float* xpp = g_xp + ((size_t)(g * 8 + w)) * BSTRIDE + c0 + 2 * l;
    float*       ghw = g_h  + ((size_t)(g * 8 + w)) * BSTRIDE + c0 + 2 * l;
    // own-block STS target: hx[buf][rank][w>>2][2l(+1)][w&3]
    float* hxo = sm + OFF_HX + rank * 512 + (w >> 2) * 256 + 8 * l + (w & 3);

    // bulk targets: peer r's hx[0][rank] block and peer r's mbar[0]
    unsigned peer_hx[8], peer_mb[8];
    {
        const unsigned hx0 = smb + OFF_HX * 4 + (unsigned)rank * BLK_BYTES;
#pragma unroll
        for (int r = 0; r < 8; r++) {
            peer_hx[r] = mapa_rank(hx0, (unsigned)r);
            peer_mb[r] = mapa_rank(mb_loc, (unsigned)r);
        }
    }
    const unsigned src_loc = smb + OFF_HX * 4 + (unsigned)rank * BLK_BYTES;

    for (int t = 0; t < S_LEN; t++) {
        const int bufw = t & 1, bufr = bufw ^ 1;

        // prefetch xp pair (warps 0-7; consumed after phase 1)
        ull xv = 0;
        if (w < 8) xv = *(const ull*)(xpp + (size_t)t * HDIM);

        // ---- phase 1: 2 col-pairs x 4 batches per lane, 32 k ----
        const float* hk = hxb + bufr * 4096;
        ull a00 = 0, a01 = 0, a02 = 0, a03 = 0;
        ull a10 = 0, a11 = 0, a12 = 0, a13 = 0;
#pragma unroll 4
        for (int k = 0; k < 32; k++) {
            ull w0 = wsp[k * 32];
            ull w1 = wsp[k * 32 + 16];
            float4 hv = *(const float4*)(hk + k * 4);
            ull h0 = splat2(hv.x), h1 = splat2(hv.y);
            ull h2 = splat2(hv.z), h3 = splat2(hv.w);
            a00 = ffma2(w0, h0, a00);
            a01 = ffma2(w0, h1, a01);
            a02 = ffma2(w0, h2, a02);
            a03 = ffma2(w0, h3, a03);
            a10 = ffma2(w1, h0, a10);
            a11 = ffma2(w1, h1, a11);
            a12 = ffma2(w1, h2, a12);
            a13 = ffma2(w1, h3, a13);
        }
        pw[0 * 32 + ls]      = a00;
        pw[1 * 32 + ls]      = a01;
        pw[2 * 32 + ls]      = a02;
        pw[3 * 32 + ls]      = a03;
        pw[0 * 32 + ls + 16] = a10;
        pw[1 * 32 + ls + 16] = a11;
        pw[2 * 32 + ls + 16] = a12;
        pw[3 * 32 + ls + 16] = a13;
        __syncthreads();

        // ---- phase 2 (warps 0-7): reduce 16 partials + xp, tanh, publish ----
        if (w < 8) {
            ull s = xv;
#pragma unroll
            for (int i = 0; i < 16; i++) s = add2(s, pr[i * 256]);
            float2 sv = upk2(s);
            float h0 = tanhf(sv.x);
            float h1 = tanhf(sv.y);
            *(float2*)(ghw + (size_t)t * HDIM) = make_float2(h0, h1);
            if (t < S_LEN - 1) {
                hxo[bufw * 4096]     = h0;   // kLocal = 2l
                hxo[bufw * 4096 + 4] = h1;   // kLocal = 2l+1
            }
        }
        if (t == S_LEN - 1) break;   // nobody needs h(S)

        __syncthreads();   // own-block STS visible + prt reads done

        if (tid < 8 && tid != rank) {
            asm volatile("fence.proxy.async.shared::cta;" ::: "memory");
            bulk_s2c(peer_hx[tid] + (unsigned)bufw * 16384u,
                     src_loc + (unsigned)bufw * 16384u,
                     BLK_BYTES,
                     peer_mb[tid] + (unsigned)bufw * 8);
        }

        // ---- wait for the 7 inbound blocks (14KB) ----
        const unsigned mbo = (unsigned)(bufw * 8);
        mbar_wait_parity(mb_loc + mbo, (unsigned)((t >> 1) & 1));
        if (tid == 0) mbar_expect_tx(mb_loc + mbo, EXPECT_TX);   // re-arm
    }
}

// ============================================================================
// Kernel C: out[M,64] = g_h[M,512] @ W_ho[512,64] + b_ho, M = 131072
// ============================================================================
__global__ void __launch_bounds__(256) out_kernel(
    const float* __restrict__ Who, const float* __restrict__ bho,
    float* __restrict__ out)
{
    __shared__ float As[128][17];
    __shared__ float Bs[16][64];
    const int tid = threadIdx.x;
    const int m0 = blockIdx.x * 128;
    const int tx = tid & 15, ty = tid >> 4;

    ull acc[8][2];
#pragma unroll
    for (int i = 0; i < 8; i++) { acc[i][0] = 0ull; acc[i][1] = 0ull; }

    for (int k0 = 0; k0 < HDIM; k0 += 16) {
#pragma unroll
        for (int i = 0; i < 2; i++) {
            int f4  = tid + i * 256;
            int row = f4 >> 2;
            int c4  = (f4 & 3) << 2;
            float4 v = *(const float4*)(g_h + (size_t)(m0 + row) * HDIM + k0 + c4);
            As[row][c4 + 0] = v.x; As[row][c4 + 1] = v.y;
            As[row][c4 + 2] = v.z; As[row][c4 + 3] = v.w;
        }
        {
            int row = tid >> 4;
            int c4  = (tid & 15) << 2;
            *(float4*)&Bs[row][c4] =
                *(const float4*)(Who + (size_t)(k0 + row) * ODIM + c4);
        }
        __syncthreads();
#pragma unroll
        for (int k = 0; k < 16; k++) {
            ulonglong2 bv = *(const ulonglong2*)&Bs[k][tx * 4];
#pragma unroll
            for (int i = 0; i < 8; i++) {
                ull a2 = splat2(As[ty * 8 + i][k]);
                acc[i][0] = ffma2(a2, bv.x, acc[i][0]);
                acc[i][1] = ffma2(a2, bv.y, acc[i][1]);
            }
        }
        __syncthreads();
    }

    float bb0 = bho[tx * 4 + 0], bb1 = bho[tx * 4 + 1];
    float bb2 = bho[tx * 4 + 2], bb3 = bho[tx * 4 + 3];
#pragma unroll
    for (int i = 0; i < 8; i++) {
        float2 v0 = upk2(acc[i][0]); v0.x += bb0; v0.y += bb1;
        float2 v1 = upk2(acc[i][1]); v1.x += bb2; v1.y += bb3;
        float* dst = out + (size_t)(m0 + ty * 8 + i) * ODIM + tx * 4;
        *(float2*)(dst + 0) = v0;
        *(float2*)(dst + 2) = v1;
    }
}

// ============================================================================
extern "C" void kernel_launch(void* const* d_in, const int* in_sizes, int n_in,
                              void* d_out, int out_size)
{
    const float* X   = (const float*)d_in[0];   // [128,1024,256]
    const float* Whh = (const float*)d_in[1];   // [512,512]
    const float* Wih = (const float*)d_in[2];   // [256,512]
    const float* bhh = (const float*)d_in[3];   // [512]
    const float* Who = (const float*)d_in[4];   // [512,64]
    const float* bho = (const float*)d_in[5];   // [64]
    float* out = (float*)d_out;                 // [128,1024,64]

    cudaFuncSetAttribute(rnn_kernel,
                         cudaFuncAttributeMaxDynamicSharedMemorySize,
                         SMEMB_BYTES);

    xproj_kernel<<<dim3(1024, 4, 1), 256>>>(X, Wih, bhh);
    dummy_kernel<<<1, 32>>>();
    dummy_kernel<<<1, 32>>>();
    rnn_kernel<<<128, 512, SMEMB_BYTES>>>(Whh);
    out_kernel<<<1024, 256>>>(Who, bho, out);
}

// round 9
// speedup vs baseline: 1.6816x; 1.1215x over previous
#include <cuda_runtime.h>
#include <cmath>

#define S_LEN  1024
#define BATCHN 128
#define IDIM   256
#define HDIM   512
#define ODIM   64

typedef unsigned long long ull;

// ---------- f32x2 packed helpers ----------
__device__ __forceinline__ ull splat2(float x) {
    ull r; asm("mov.b64 %0, {%1, %1};" : "=l"(r) : "f"(x)); return r;
}
__device__ __forceinline__ ull ffma2(ull a, ull b, ull c) {
    ull d; asm("fma.rn.f32x2 %0, %1, %2, %3;" : "=l"(d) : "l"(a), "l"(b), "l"(c)); return d;
}
__device__ __forceinline__ ull add2(ull a, ull b) {
    ull d; asm("add.rn.f32x2 %0, %1, %2;" : "=l"(d) : "l"(a), "l"(b)); return d;
}
__device__ __forceinline__ float2 upk2(ull v) {
    float2 f; asm("mov.b64 {%0, %1}, %2;" : "=f"(f.x), "=f"(f.y) : "l"(v)); return f;
}
__device__ __forceinline__ unsigned s2u32(const void* p) {
    unsigned a;
    asm("{ .reg .u64 t; cvta.to.shared.u64 t, %1; cvt.u32.u64 %0, t; }" : "=r"(a) : "l"(p));
    return a;
}
__device__ __forceinline__ unsigned mapa_rank(unsigned a, unsigned r) {
    unsigned d; asm("mapa.shared::cluster.u32 %0, %1, %2;" : "=r"(d) : "r"(a), "r"(r));
    return d;
}
__device__ __forceinline__ void bulk_s2c(unsigned dst, unsigned src, unsigned bytes,
                                         unsigned mbar) {
    asm volatile(
        "cp.async.bulk.shared::cluster.shared::cta.mbarrier::complete_tx::bytes "
        "[%0], [%1], %2, [%3];"
        :: "r"(dst), "r"(src), "r"(bytes), "r"(mbar) : "memory");
}
__device__ __forceinline__ void mbar_init(unsigned mbar, unsigned cnt) {
    asm volatile("mbarrier.init.shared.b64 [%0], %1;" :: "r"(mbar), "r"(cnt) : "memory");
}
__device__ __forceinline__ void mbar_expect_tx(unsigned mbar, unsigned bytes) {
    asm volatile("mbarrier.arrive.expect_tx.shared.b64 _, [%0], %1;"
                 :: "r"(mbar), "r"(bytes) : "memory");
}
__device__ __forceinline__ void mbar_wait_parity(unsigned mbar, unsigned parity) {
    asm volatile(
        "{\n\t"
        ".reg .pred P;\n"
        "LW_%=:\n\t"
        "mbarrier.try_wait.parity.acquire.cta.shared::cta.b64 P, [%0], %1, 0x989680;\n\t"
        "@P bra LD_%=;\n\t"
        "bra LW_%=;\n"
        "LD_%=:\n\t"
        "}"
        :: "r"(mbar), "r"(parity) : "memory");
}
__device__ __forceinline__ unsigned elect1() {
    unsigned p;
    asm volatile("{\n\t.reg .pred p;\n\telect.sync _|p, 0xFFFFFFFF;\n\t"
                 "selp.b32 %0, 1, 0, p;\n\t}" : "=r"(p));
    return p;
}

// ---------- scratch (device globals: allocation-free rule) ----------
__device__ float g_xp[(size_t)BATCHN * S_LEN * HDIM];  // X@W_ih + b_hh, [b][s][h]
__device__ float g_h [(size_t)BATCHN * S_LEN * HDIM];  // hidden states,  [b][s][h]

// ============================================================================
// Kernel A: g_xp[M,512] = X[M,256] @ W_ih[256,512] + b_hh, M = 131072
// ============================================================================
__global__ void __launch_bounds__(256, 2) xproj_kernel(
    const float* __restrict__ X, const float* __restrict__ Wih,
    const float* __restrict__ bhh)
{
    __shared__ float As[128][17];
    __shared__ float Bs[16][128];
    const int tid = threadIdx.x;
    const int m0 = blockIdx.x * 128;
    const int n0 = blockIdx.y * 128;
    const int tx = tid & 15, ty = tid >> 4;

    ull acc[8][4];
#pragma unroll
    for (int i = 0; i < 8; i++)
#pragma unroll
        for (int j = 0; j < 4; j++) acc[i][j] = 0ull;

    for (int k0 = 0; k0 < IDIM; k0 += 16) {
#pragma unroll
        for (int i = 0; i < 2; i++) {
            int f4  = tid + i * 256;
            int row = f4 >> 2;
            int c4  = (f4 & 3) << 2;
            float4 v = *(const float4*)(X + (size_t)(m0 + row) * IDIM + k0 + c4);
            As[row][c4 + 0] = v.x; As[row][c4 + 1] = v.y;
            As[row][c4 + 2] = v.z; As[row][c4 + 3] = v.w;
        }
#pragma unroll
        for (int i = 0; i < 2; i++) {
            int f4  = tid + i * 256;
            int row = f4 >> 5;
            int c4  = (f4 & 31) << 2;
            *(float4*)&Bs[row][c4] =
                *(const float4*)(Wih + (size_t)(k0 + row) * HDIM + n0 + c4);
        }
        __syncthreads();
#pragma unroll
        for (int k = 0; k < 16; k++) {
            ulonglong2 bv0 = *(const ulonglong2*)&Bs[k][tx * 4];
            ulonglong2 bv1 = *(const ulonglong2*)&Bs[k][64 + tx * 4];
#pragma unroll
            for (int i = 0; i < 8; i++) {
                ull a2 = splat2(As[ty * 8 + i][k]);
                acc[i][0] = ffma2(a2, bv0.x, acc[i][0]);
                acc[i][1] = ffma2(a2, bv0.y, acc[i][1]);
                acc[i][2] = ffma2(a2, bv1.x, acc[i][2]);
                acc[i][3] = ffma2(a2, bv1.y, acc[i][3]);
            }
        }
        __syncthreads();
    }

#pragma unroll
    for (int i = 0; i < 8; i++) {
        float* dst = g_xp + (size_t)(m0 + ty * 8 + i) * HDIM + n0;
#pragma unroll
        for (int j = 0; j < 4; j++) {
            int n = (j < 2) ? (tx * 4 + j * 2) : (64 + tx * 4 + (j - 2) * 2);
            float2 v = upk2(acc[i][j]);
            v.x += bhh[n0 + n];
            v.y += bhh[n0 + n + 1];
            *(float2*)(dst + n) = v;
        }
    }
}

// empty launch to shift ncu's fixed profiled-launch slot onto rnn_kernel
__global__ void dummy_kernel() {}

// ============================================================================
// Kernel B: serial recurrence. 16 clusters x 8 CTAs; rank r owns W_hh cols
// [64r,64r+64) as ull col-pairs in smem; cluster g owns batch rows [8g,8g+8).
// 512 threads (16 warps).
//
// R9 delta vs R7: PER-SOURCE mbarriers. mb[src][slot] (16 total), each
// expect_tx = 2048 B (one source block). Warp pair (2s, 2s+1) waits only on
// source s at top-of-loop (xp LDG prefetched into the wait shadow); warps
// whose source == own rank skip the wait (self block ordered by syncthreads).
// Even warp of each pair re-arms its barrier post-wait.
//
// hx layout per slot (16KB): [src 8][grp 2][kLocal 64][bi 4] floats.
// Slot schedule: step t reads slot (t&1)^1 (h(t-1)), writes slot t&1 (h(t)).
// ============================================================================
#define NT 512
// float offsets: Wp ull[512][32] | prt ull[16][8][32] | hx f32[2][8][512] | mb
#define OFF_PRT 32768
#define OFF_HX  40960
#define OFF_MB  49152                 // 16 mbarriers = 128 B = 32 floats
#define SMEMB_BYTES ((49152 + 32) * 4)
#define BSTRIDE ((size_t)S_LEN * HDIM)
#define BLK_BYTES 2048u               // one src-rank block

__global__ void __launch_bounds__(NT, 1) __cluster_dims__(8, 1, 1)
rnn_kernel(const float* __restrict__ Whh)
{
    extern __shared__ float sm[];
    ull* Wp  = (ull*)sm;               // [k][jp], k stride 32 ull
    ull* prt = (ull*)(sm + OFF_PRT);   // [w16][b][jp]

    const int tid  = threadIdx.x;
    const int rank = blockIdx.x & 7;
    const int g    = blockIdx.x >> 3;
    const int c0   = rank * 64;
    const unsigned smb    = s2u32(sm);
    const unsigned mb_loc = smb + OFF_MB * 4;   // mb[src][slot]: +(src*2+slot)*8

    if (tid == 0) {
#pragma unroll
        for (int i = 0; i < 16; i++) {
            mbar_init(mb_loc + i * 8, 1);
            mbar_expect_tx(mb_loc + i * 8, BLK_BYTES);
        }
    }

    // Load W_hh slice once as column pairs (128KB)
    for (int i = tid; i < HDIM * 32; i += NT) {
        int k = i >> 5, jp = i & 31;
        *(float2*)(Wp + i) = *(const float2*)(Whh + (size_t)k * HDIM + c0 + 2 * jp);
    }
    // zero hx (h0 = 0), both slots
    for (int i = tid; i < 2 * 8 * HDIM; i += NT) sm[OFF_HX + i] = 0.f;
    __syncthreads();
    asm volatile("barrier.cluster.arrive.aligned;" ::: "memory");
    asm volatile("barrier.cluster.wait.aligned;"   ::: "memory");

    const int w  = tid >> 5, l = tid & 31;
    const int rg = l >> 4,  ls = l & 15;
    const int kbeg = w * 32;
    const int sw   = w >> 1;            // source rank feeding this warp's k-chunk

    // phase-1 pointers
    const ull*   wsp = Wp + (size_t)kbeg * 32 + ls;   // wsp[k*32], wsp[k*32+16]
    const float* hxb = sm + OFF_HX + sw * 512 + rg * 256 + (w & 1) * 128;
    ull*         pw  = prt + w * 256 + (rg * 4) * 32; // + q*32 + ls (+16)

    // phase-2 mapping (warps 0-7): b = w, lane l = col-pair jp
    const ull* pr = prt + w * 32 + l;
    const float* xpp = g_xp + ((size_t)(g * 8 + w)) * BSTRIDE + c0 + 2 * l;
    float*       ghw = g_h  + ((size_t)(g * 8 + w)) * BSTRIDE + c0 + 2 * l;
    // own-block STS target: hx[slot][rank][w>>2][2l(+1)][w&3]
    float* hxo = sm + OFF_HX + rank * 512 + (w >> 2) * 256 + 8 * l + (w & 3);

    // bulk targets: peer r's hx[0][rank] block + peer r's mb[rank][0]
    unsigned peer_hx[8], peer_mb[8];
    {
        const unsigned hx0 = smb + OFF_HX * 4 + (unsigned)rank * BLK_BYTES;
        const unsigned mb0 = mb_loc + (unsigned)(rank * 16);
#pragma unroll
        for (int r = 0; r < 8; r++) {
            peer_hx[r] = mapa_rank(hx0, (unsigned)r);
            peer_mb[r] = mapa_rank(mb0, (unsigned)r);
        }
    }
    const unsigned src_loc = smb + OFF_HX * 4 + (unsigned)rank * BLK_BYTES;
    const unsigned mb_src  = mb_loc + (unsigned)(sw * 16);
    const bool self_src    = (sw == rank);
    const bool rearm_warp  = ((w & 1) == 0);

    for (int t = 0; t < S_LEN; t++) {
        const int wb = t & 1, rb = wb ^ 1;

        // xp prefetch (warps 0-7), issued before the wait so it rides it
        ull xv = 0;
        if (w < 8) xv = *(const ull*)(xpp + (size_t)t * HDIM);

        // ---- per-source wait: only this warp's source block ----
        if (t > 0 && !self_src) {
            const unsigned mb = mb_src + (unsigned)(rb * 8);
            mbar_wait_parity(mb, (unsigned)(((t - 1) >> 1) & 1));
            if (rearm_warp && elect1()) mbar_expect_tx(mb, BLK_BYTES);
        }

        // ---- phase 1: 2 col-pairs x 4 batches per lane, 32 k ----
        const float* hk = hxb + rb * 4096;
        ull a00 = 0, a01 = 0, a02 = 0, a03 = 0;
        ull a10 = 0, a11 = 0, a12 = 0, a13 = 0;
#pragma unroll 4
        for (int k = 0; k < 32; k++) {
            ull w0 = wsp[k * 32];
            ull w1 = wsp[k * 32 + 16];
            float4 hv = *(const float4*)(hk + k * 4);
            ull h0 = splat2(hv.x), h1 = splat2(hv.y);
            ull h2 = splat2(hv.z), h3 = splat2(hv.w);
            a00 = ffma2(w0, h0, a00);
            a01 = ffma2(w0, h1, a01);
            a02 = ffma2(w0, h2, a02);
            a03 = ffma2(w0, h3, a03);
            a10 = ffma2(w1, h0, a10);
            a11 = ffma2(w1, h1, a11);
            a12 = ffma2(w1, h2, a12);
            a13 = ffma2(w1, h3, a13);
        }
        pw[0 * 32 + ls]      = a00;
        pw[1 * 32 + ls]      = a01;
        pw[2 * 32 + ls]      = a02;
        pw[3 * 32 + ls]      = a03;
        pw[0 * 32 + ls + 16] = a10;
        pw[1 * 32 + ls + 16] = a11;
        pw[2 * 32 + ls + 16] = a12;
        pw[3 * 32 + ls + 16] = a13;
        __syncthreads();

        // ---- phase 2 (warps 0-7): reduce 16 partials + xp, tanh, publish ----
        if (w < 8) {
            ull s = xv;
#pragma unroll
            for (int i = 0; i < 16; i++) s = add2(s, pr[i * 256]);
            float2 sv = upk2(s);
            float h0 = tanhf(sv.x);
            float h1 = tanhf(sv.y);
            *(float2*)(ghw + (size_t)t * HDIM) = make_float2(h0, h1);
            if (t < S_LEN - 1) {
                hxo[wb * 4096]     = h0;   // kLocal = 2l
                hxo[wb * 4096 + 4] = h1;   // kLocal = 2l+1
            }
        }
        if (t == S_LEN - 1) break;   // nobody needs h(S)

        __syncthreads();   // own-block STS visible + prt reads done

        if (tid < 8 && tid != rank) {
            asm volatile("fence.proxy.async.shared::cta;" ::: "memory");
            bulk_s2c(peer_hx[tid] + (unsigned)wb * 16384u,
                     src_loc + (unsigned)wb * 16384u,
                     BLK_BYTES,
                     peer_mb[tid] + (unsigned)wb * 8);
        }
    }
}

// ============================================================================
// Kernel C: out[M,64] = g_h[M,512] @ W_ho[512,64] + b_ho, M = 131072
// ============================================================================
__global__ void __launch_bounds__(256) out_kernel(
    const float* __restrict__ Who, const float* __restrict__ bho,
    float* __restrict__ out)
{
    __shared__ float As[128][17];
    __shared__ float Bs[16][64];
    const int tid = threadIdx.x;
    const int m0 = blockIdx.x * 128;
    const int tx = tid & 15, ty = tid >> 4;

    ull acc[8][2];
#pragma unroll
    for (int i = 0; i < 8; i++) { acc[i][0] = 0ull; acc[i][1] = 0ull; }

    for (int k0 = 0; k0 < HDIM; k0 += 16) {
#pragma unroll
        for (int i = 0; i < 2; i++) {
            int f4  = tid + i * 256;
            int row = f4 >> 2;
            int c4  = (f4 & 3) << 2;
            float4 v = *(const float4*)(g_h + (size_t)(m0 + row) * HDIM + k0 + c4);
            As[row][c4 + 0] = v.x; As[row][c4 + 1] = v.y;
            As[row][c4 + 2] = v.z; As[row][c4 + 3] = v.w;
        }
        {
            int row = tid >> 4;
            int c4  = (tid & 15) << 2;
            *(float4*)&Bs[row][c4] =
                *(const float4*)(Who + (size_t)(k0 + row) * ODIM + c4);
        }
        __syncthreads();
#pragma unroll
        for (int k = 0; k < 16; k++) {
            ulonglong2 bv = *(const ulonglong2*)&Bs[k][tx * 4];
#pragma unroll
            for (int i = 0; i < 8; i++) {
                ull a2 = splat2(As[ty * 8 + i][k]);
                acc[i][0] = ffma2(a2, bv.x, acc[i][0]);
                acc[i][1] = ffma2(a2, bv.y, acc[i][1]);
            }
        }
        __syncthreads();
    }

    float bb0 = bho[tx * 4 + 0], bb1 = bho[tx * 4 + 1];
    float bb2 = bho[tx * 4 + 2], bb3 = bho[tx * 4 + 3];
#pragma unroll
    for (int i = 0; i < 8; i++) {
        float2 v0 = upk2(acc[i][0]); v0.x += bb0; v0.y += bb1;
        float2 v1 = upk2(acc[i][1]); v1.x += bb2; v1.y += bb3;
        float* dst = out + (size_t)(m0 + ty * 8 + i) * ODIM + tx * 4;
        *(float2*)(dst + 0) = v0;
        *(float2*)(dst + 2) = v1;
    }
}

// ============================================================================
extern "C" void kernel_launch(void* const* d_in, const int* in_sizes, int n_in,
                              void* d_out, int out_size)
{
    const float* X   = (const float*)d_in[0];   // [128,1024,256]
    const float* Whh = (const float*)d_in[1];   // [512,512]
    const float* Wih = (const float*)d_in[2];   // [256,512]
    const float* bhh = (const float*)d_in[3];   // [512]
    const float* Who = (const float*)d_in[4];   // [512,64]
    const float* bho = (const float*)d_in[5];   // [64]
    float* out = (float*)d_out;                 // [128,1024,64]

    cudaFuncSetAttribute(rnn_kernel,
                         cudaFuncAttributeMaxDynamicSharedMemorySize,
                         SMEMB_BYTES);

    xproj_kernel<<<dim3(1024, 4, 1), 256>>>(X, Wih, bhh);
    dummy_kernel<<<1, 32>>>();
    dummy_kernel<<<1, 32>>>();
    rnn_kernel<<<128, NT, SMEMB_BYTES>>>(Whh);
    out_kernel<<<1024, 256>>>(Who, bho, out);
}